// round 2
// baseline (speedup 1.0000x reference)
#include <cuda_runtime.h>
#include <cstdint>
#include <cstddef>

// ---------------------------------------------------------------------------
// Problem constants (FluxIPAttnProcessor: B=1, S=2048, H=24, D=128)
// ---------------------------------------------------------------------------
#define S_LEN 2048
#define HIDN  3072
#define NH    24
#define HD    128
#define IPSEQ 512
#define IPDIM 1152

#define DEV_INLINE __device__ __forceinline__

// ---------------------------------------------------------------------------
// Packed fp32x2 helpers (Blackwell FFMA2 path, PTX-only)
// ---------------------------------------------------------------------------
DEV_INLINE unsigned long long pack2(float lo, float hi) {
    unsigned long long r;
    asm("mov.b64 %0, {%1, %2};"
        : "=l"(r) : "r"(__float_as_uint(lo)), "r"(__float_as_uint(hi)));
    return r;
}
DEV_INLINE void unpack2(unsigned long long v, float& lo, float& hi) {
    unsigned int a, b;
    asm("mov.b64 {%0, %1}, %2;" : "=r"(a), "=r"(b) : "l"(v));
    lo = __uint_as_float(a); hi = __uint_as_float(b);
}
DEV_INLINE void fma2(unsigned long long& d, unsigned long long a, unsigned long long b) {
    asm("fma.rn.f32x2 %0, %1, %2, %0;" : "+l"(d) : "l"(a), "l"(b));
}
DEV_INLINE void mul2(unsigned long long& d, unsigned long long a) {
    asm("mul.rn.f32x2 %0, %0, %1;" : "+l"(d) : "l"(a));
}

// ---------------------------------------------------------------------------
// Device scratch (static __device__ arrays: allocation-free rule)
// ---------------------------------------------------------------------------
__device__ float g_q   [S_LEN * HIDN];
__device__ float g_k   [S_LEN * HIDN];
__device__ float g_v   [S_LEN * HIDN];
__device__ float g_qr  [S_LEN * HIDN];
__device__ float g_qn  [S_LEN * HIDN];
__device__ float g_kr  [S_LEN * HIDN];
__device__ float g_kip [IPSEQ * HIDN];
__device__ float g_kipn[IPSEQ * HIDN];
__device__ float g_vip [IPSEQ * HIDN];
__device__ float g_ao  [S_LEN * HIDN];

// ---------------------------------------------------------------------------
// GEMM: C[M,N] = A[M,K] * B[N,K]^T + bias[N]
// Tiles 128x128x16, 256 threads, 8x8 per thread, packed f32x2 accumulators.
// Requires M%128==0, N%128==0, K%16==0 (true for all call sites).
// ---------------------------------------------------------------------------
__global__ void __launch_bounds__(256, 2) gemm_nt_bias(
    const float* __restrict__ A, const float* __restrict__ B,
    const float* __restrict__ bias, float* __restrict__ C,
    int M, int N, int K)
{
    __shared__ float As[16][128];
    __shared__ float Bs[16][128];
    const int tid = threadIdx.x;
    const int m0  = blockIdx.y * 128;
    const int n0  = blockIdx.x * 128;
    const int ty  = tid >> 4;
    const int tx  = tid & 15;

    unsigned long long acc[8][4];
#pragma unroll
    for (int i = 0; i < 8; i++)
#pragma unroll
        for (int j = 0; j < 4; j++) acc[i][j] = 0ull;

    const int lrow = tid >> 2;          // 0..63
    const int lkc  = (tid & 3) * 4;     // 0,4,8,12
    const float* Ap  = A + (size_t)(m0 + lrow) * K + lkc;
    const float* Ap2 = Ap + (size_t)64 * K;
    const float* Bp  = B + (size_t)(n0 + lrow) * K + lkc;
    const float* Bp2 = Bp + (size_t)64 * K;

    for (int k0 = 0; k0 < K; k0 += 16) {
        float4 a0 = *(const float4*)(Ap  + k0);
        float4 a1 = *(const float4*)(Ap2 + k0);
        float4 b0 = *(const float4*)(Bp  + k0);
        float4 b1 = *(const float4*)(Bp2 + k0);
        __syncthreads();
        As[lkc + 0][lrow]      = a0.x; As[lkc + 1][lrow]      = a0.y;
        As[lkc + 2][lrow]      = a0.z; As[lkc + 3][lrow]      = a0.w;
        As[lkc + 0][lrow + 64] = a1.x; As[lkc + 1][lrow + 64] = a1.y;
        As[lkc + 2][lrow + 64] = a1.z; As[lkc + 3][lrow + 64] = a1.w;
        Bs[lkc + 0][lrow]      = b0.x; Bs[lkc + 1][lrow]      = b0.y;
        Bs[lkc + 2][lrow]      = b0.z; Bs[lkc + 3][lrow]      = b0.w;
        Bs[lkc + 0][lrow + 64] = b1.x; Bs[lkc + 1][lrow + 64] = b1.y;
        Bs[lkc + 2][lrow + 64] = b1.z; Bs[lkc + 3][lrow + 64] = b1.w;
        __syncthreads();
#pragma unroll
        for (int k = 0; k < 16; k++) {
            float av[8];
            *(float4*)&av[0] = *(const float4*)&As[k][ty * 8];
            *(float4*)&av[4] = *(const float4*)&As[k][ty * 8 + 4];
            unsigned long long bv[4];
#pragma unroll
            for (int jp = 0; jp < 4; jp++)
                bv[jp] = *(const unsigned long long*)&Bs[k][tx * 8 + jp * 2];
#pragma unroll
            for (int i = 0; i < 8; i++) {
                unsigned long long ad = pack2(av[i], av[i]);
#pragma unroll
                for (int jp = 0; jp < 4; jp++) fma2(acc[i][jp], ad, bv[jp]);
            }
        }
    }

    float bl[8];
    *(float4*)&bl[0] = *(const float4*)&bias[n0 + tx * 8];
    *(float4*)&bl[4] = *(const float4*)&bias[n0 + tx * 8 + 4];
#pragma unroll
    for (int i = 0; i < 8; i++) {
        const int m = m0 + ty * 8 + i;
        float cv[8];
#pragma unroll
        for (int jp = 0; jp < 4; jp++) unpack2(acc[i][jp], cv[2 * jp], cv[2 * jp + 1]);
#pragma unroll
        for (int j = 0; j < 8; j++) cv[j] += bl[j];
        float* cp = C + (size_t)m * N + n0 + tx * 8;
        *(float4*)(cp)     = make_float4(cv[0], cv[1], cv[2], cv[3]);
        *(float4*)(cp + 4) = make_float4(cv[4], cv[5], cv[6], cv[7]);
    }
}

// ---------------------------------------------------------------------------
// Prep kernels: RoPE + RMSNorm. One block = one (seq, head) row of 128.
// ---------------------------------------------------------------------------
DEV_INLINE float blk_sumsq(float x, float* red, int d) {
    float v = x * x;
#pragma unroll
    for (int o = 16; o > 0; o >>= 1) v += __shfl_xor_sync(0xffffffffu, v, o);
    if ((d & 31) == 0) red[d >> 5] = v;
    __syncthreads();
    return red[0] + red[1] + red[2] + red[3];
}

__global__ void prep_q_kernel(const float* __restrict__ q,
                              const float* __restrict__ sinp, const float* __restrict__ cosp,
                              const float* __restrict__ qscale,
                              float* __restrict__ qrot, float* __restrict__ qnorm)
{
    __shared__ float red[4];
    const int s = blockIdx.x, hh = blockIdx.y, d = threadIdx.x;
    const size_t base = (size_t)s * HIDN + hh * HD;
    const float x = q[base + d];
    const float ss = blk_sumsq(x, red, d);
    const float rms = sqrtf(ss * (1.0f / 128.0f));
    const float inv = 1.0f / (rms + 1e-6f);
    qnorm[base + d] = qscale[d] * x * inv * 0.08838834764831845f;  // 128^-0.5
    float outv;
    if (d < 64) {
        float rot = (d < 32) ? -q[base + d + 32] : q[base + d - 32];
        outv = x * cosp[s * 64 + d] + rot * sinp[s * 64 + d];
    } else {
        outv = x;
    }
    qrot[base + d] = outv;
}

__global__ void prep_k_kernel(const float* __restrict__ k,
                              const float* __restrict__ sinp, const float* __restrict__ cosp,
                              float* __restrict__ krot)
{
    const int s = blockIdx.x, hh = blockIdx.y, d = threadIdx.x;
    const size_t base = (size_t)s * HIDN + hh * HD;
    const float x = k[base + d];
    float outv;
    if (d < 64) {
        float rot = (d < 32) ? -k[base + d + 32] : k[base + d - 32];
        outv = x * cosp[s * 64 + d] + rot * sinp[s * 64 + d];
    } else {
        outv = x;
    }
    krot[base + d] = outv;
}

__global__ void prep_kip_kernel(const float* __restrict__ kip,
                                const float* __restrict__ kscale,
                                float* __restrict__ kipn)
{
    __shared__ float red[4];
    const int s = blockIdx.x, hh = blockIdx.y, d = threadIdx.x;
    const size_t base = (size_t)s * HIDN + hh * HD;
    const float x = kip[base + d];
    const float ss = blk_sumsq(x, red, d);
    const float rms = sqrtf(ss * (1.0f / 128.0f));
    const float inv = 1.0f / (rms + 1e-6f);
    kipn[base + d] = kscale[d] * x * inv * 0.08838834764831845f;
}

// ---------------------------------------------------------------------------
// Fused two-context flash attention.
// Grid: (S/128, H). 256 threads. Each CTA: 128 q-rows x one head.
// Pass 0: softmax(q_rot k_rot^T) v  over 2048 keys  -> write out/l
// Pass 1: softmax(q_norm kipn^T) vip over 512 keys  -> accumulate into out
// smem: Qt[128][129] (d-major), Kt[128][65] (d-major), Vs[64][128], Ps[128][64]
// ---------------------------------------------------------------------------
#define AQ 128
#define AK 64
#define QT_STRIDE 129
#define KT_STRIDE 65
#define ATTN_SMEM_FLOATS (128 * QT_STRIDE + 128 * KT_STRIDE + AK * 128 + AQ * AK)

__global__ void __launch_bounds__(256, 1) attn_kernel(
    const float* __restrict__ qr,   const float* __restrict__ qn,
    const float* __restrict__ kr,   const float* __restrict__ vv,
    const float* __restrict__ kipn, const float* __restrict__ vip,
    float* __restrict__ out)
{
    extern __shared__ float sm[];
    float* Qt = sm;                            // 128 * 129
    float* Kt = Qt + 128 * QT_STRIDE;          // 128 * 65
    float* Vs = Kt + 128 * KT_STRIDE;          // 64 * 128
    float* Ps = Vs + AK * 128;                 // 128 * 64

    const int h    = blockIdx.y;
    const int q0   = blockIdx.x * AQ;
    const int tid  = threadIdx.x;
    const int ty   = tid >> 4;
    const int tx   = tid & 15;
    const int hofs = h * HD;

#pragma unroll 1
    for (int pass = 0; pass < 2; pass++) {
        const float* Qsrc = pass ? qn   : qr;
        const float* Ksrc = pass ? kipn : kr;
        const float* Vsrc = pass ? vip  : vv;
        const int nk = pass ? IPSEQ : S_LEN;

        __syncthreads();  // Qt reuse across passes
        // Load Q tile (128 rows x 128 d) into Qt[d][r]
#pragma unroll
        for (int it = 0; it < 16; it++) {
            int f  = tid + it * 256;
            int r  = f >> 5;
            int d4 = (f & 31) * 4;
            float4 q4 = *(const float4*)&Qsrc[(size_t)(q0 + r) * HIDN + hofs + d4];
            Qt[(d4 + 0) * QT_STRIDE + r] = q4.x;
            Qt[(d4 + 1) * QT_STRIDE + r] = q4.y;
            Qt[(d4 + 2) * QT_STRIDE + r] = q4.z;
            Qt[(d4 + 3) * QT_STRIDE + r] = q4.w;
        }

        float mrow[8], lrow[8];
        unsigned long long o[8][4];
#pragma unroll
        for (int i = 0; i < 8; i++) {
            mrow[i] = -1e30f; lrow[i] = 0.0f;
#pragma unroll
            for (int jp = 0; jp < 4; jp++) o[i][jp] = 0ull;
        }

#pragma unroll 1
        for (int kt = 0; kt < nk; kt += AK) {
            __syncthreads();  // protect Kt/Vs (and Qt on first iter)
            // K tile -> Kt[d][c]
#pragma unroll
            for (int it = 0; it < 8; it++) {
                int f  = tid + it * 256;
                int c  = f >> 5;
                int d4 = (f & 31) * 4;
                float4 k4 = *(const float4*)&Ksrc[(size_t)(kt + c) * HIDN + hofs + d4];
                Kt[(d4 + 0) * KT_STRIDE + c] = k4.x;
                Kt[(d4 + 1) * KT_STRIDE + c] = k4.y;
                Kt[(d4 + 2) * KT_STRIDE + c] = k4.z;
                Kt[(d4 + 3) * KT_STRIDE + c] = k4.w;
            }
            // V tile -> Vs[k][c] (natural)
#pragma unroll
            for (int it = 0; it < 8; it++) {
                int f  = tid + it * 256;
                int r  = f >> 5;
                int c4 = (f & 31) * 4;
                *(float4*)&Vs[r * 128 + c4] =
                    *(const float4*)&Vsrc[(size_t)(kt + r) * HIDN + hofs + c4];
            }
            __syncthreads();

            // S = Q K^T : thread tile 8 rows x 4 cols, packed pairs on cols
            unsigned long long sp[8][2];
#pragma unroll
            for (int i = 0; i < 8; i++) { sp[i][0] = 0ull; sp[i][1] = 0ull; }
#pragma unroll 4
            for (int d = 0; d < 128; d++) {
                const float* qrow = &Qt[d * QT_STRIDE + ty * 8];
                const float* krow = &Kt[d * KT_STRIDE + tx * 4];
                unsigned long long kp0 = pack2(krow[0], krow[1]);
                unsigned long long kp1 = pack2(krow[2], krow[3]);
#pragma unroll
                for (int i = 0; i < 8; i++) {
                    unsigned long long qd = pack2(qrow[i], qrow[i]);
                    fma2(sp[i][0], qd, kp0);
                    fma2(sp[i][1], qd, kp1);
                }
            }

            // Online softmax update + write P tile
#pragma unroll
            for (int i = 0; i < 8; i++) {
                float s0, s1, s2, s3;
                unpack2(sp[i][0], s0, s1);
                unpack2(sp[i][1], s2, s3);
                float mx = fmaxf(fmaxf(s0, s1), fmaxf(s2, s3));
#pragma unroll
                for (int msk = 1; msk < 16; msk <<= 1)
                    mx = fmaxf(mx, __shfl_xor_sync(0xffffffffu, mx, msk));
                const float mn = fmaxf(mrow[i], mx);
                const float alpha = __expf(mrow[i] - mn);
                const float p0 = __expf(s0 - mn);
                const float p1 = __expf(s1 - mn);
                const float p2 = __expf(s2 - mn);
                const float p3 = __expf(s3 - mn);
                float rs = (p0 + p1) + (p2 + p3);
#pragma unroll
                for (int msk = 1; msk < 16; msk <<= 1)
                    rs += __shfl_xor_sync(0xffffffffu, rs, msk);
                lrow[i] = lrow[i] * alpha + rs;
                mrow[i] = mn;
                unsigned long long ad = pack2(alpha, alpha);
#pragma unroll
                for (int jp = 0; jp < 4; jp++) mul2(o[i][jp], ad);
                *(float4*)&Ps[(ty * 8 + i) * AK + tx * 4] = make_float4(p0, p1, p2, p3);
            }
            __syncthreads();

            // O += P V : thread tile 8 rows x 8 cols (packed pairs)
#pragma unroll 2
            for (int k = 0; k < AK; k++) {
                unsigned long long vp[4];
#pragma unroll
                for (int jp = 0; jp < 4; jp++)
                    vp[jp] = *(const unsigned long long*)&Vs[k * 128 + tx * 8 + jp * 2];
#pragma unroll
                for (int i = 0; i < 8; i++) {
                    const float p = Ps[(ty * 8 + i) * AK + k];
                    unsigned long long pd = pack2(p, p);
#pragma unroll
                    for (int jp = 0; jp < 4; jp++) fma2(o[i][jp], pd, vp[jp]);
                }
            }
        }

        // Finalize: pass 0 stores out = o/l, pass 1 accumulates
#pragma unroll
        for (int i = 0; i < 8; i++) {
            const float invl = 1.0f / lrow[i];
            float ov[8];
#pragma unroll
            for (int jp = 0; jp < 4; jp++) unpack2(o[i][jp], ov[2 * jp], ov[2 * jp + 1]);
#pragma unroll
            for (int j = 0; j < 8; j++) ov[j] *= invl;
            float* op = out + (size_t)(q0 + ty * 8 + i) * HIDN + hofs + tx * 8;
            if (pass == 0) {
                *(float4*)(op)     = make_float4(ov[0], ov[1], ov[2], ov[3]);
                *(float4*)(op + 4) = make_float4(ov[4], ov[5], ov[6], ov[7]);
            } else {
                float4 e0 = *(float4*)(op);
                float4 e1 = *(float4*)(op + 4);
                e0.x += ov[0]; e0.y += ov[1]; e0.z += ov[2]; e0.w += ov[3];
                e1.x += ov[4]; e1.y += ov[5]; e1.z += ov[6]; e1.w += ov[7];
                *(float4*)(op)     = e0;
                *(float4*)(op + 4) = e1;
            }
        }
    }
}

// ---------------------------------------------------------------------------
// Launch
// ---------------------------------------------------------------------------
extern "C" void kernel_launch(void* const* d_in, const int* in_sizes, int n_in,
                              void* d_out, int out_size)
{
    const float* hidden = (const float*)d_in[0];
    const float* iph    = (const float*)d_in[1];
    const float* sinp   = (const float*)d_in[2];
    const float* cosp   = (const float*)d_in[3];
    const float* Wq     = (const float*)d_in[4];
    const float* bq     = (const float*)d_in[5];
    const float* Wk     = (const float*)d_in[6];
    const float* bk     = (const float*)d_in[7];
    const float* Wv     = (const float*)d_in[8];
    const float* bv     = (const float*)d_in[9];
    const float* Wo     = (const float*)d_in[10];
    const float* bo     = (const float*)d_in[11];
    const float* Wk_ip  = (const float*)d_in[12];
    const float* bk_ip  = (const float*)d_in[13];
    const float* Wv_ip  = (const float*)d_in[14];
    const float* bv_ip  = (const float*)d_in[15];
    const float* qscale = (const float*)d_in[16];
    const float* kscale = (const float*)d_in[17];

    float *q, *k, *v, *qr, *qn, *kr, *kip, *kipn, *vip, *ao;
    cudaGetSymbolAddress((void**)&q,    g_q);
    cudaGetSymbolAddress((void**)&k,    g_k);
    cudaGetSymbolAddress((void**)&v,    g_v);
    cudaGetSymbolAddress((void**)&qr,   g_qr);
    cudaGetSymbolAddress((void**)&qn,   g_qn);
    cudaGetSymbolAddress((void**)&kr,   g_kr);
    cudaGetSymbolAddress((void**)&kip,  g_kip);
    cudaGetSymbolAddress((void**)&kipn, g_kipn);
    cudaGetSymbolAddress((void**)&vip,  g_vip);
    cudaGetSymbolAddress((void**)&ao,   g_ao);

    const dim3 blk(256);
    const dim3 g_big(HIDN / 128, S_LEN / 128);   // (24, 16)
    const dim3 g_ip (HIDN / 128, IPSEQ / 128);   // (24, 4)

    // Projections
    gemm_nt_bias<<<g_big, blk>>>(hidden, Wq, bq, q, S_LEN, HIDN, HIDN);
    gemm_nt_bias<<<g_big, blk>>>(hidden, Wk, bk, k, S_LEN, HIDN, HIDN);
    gemm_nt_bias<<<g_big, blk>>>(hidden, Wv, bv, v, S_LEN, HIDN, HIDN);
    gemm_nt_bias<<<g_ip,  blk>>>(iph, Wk_ip, bk_ip, kip, IPSEQ, HIDN, IPDIM);
    gemm_nt_bias<<<g_ip,  blk>>>(iph, Wv_ip, bv_ip, vip, IPSEQ, HIDN, IPDIM);

    // RoPE / RMSNorm prep
    prep_q_kernel  <<<dim3(S_LEN, NH), 128>>>(q, sinp, cosp, qscale, qr, qn);
    prep_k_kernel  <<<dim3(S_LEN, NH), 128>>>(k, sinp, cosp, kr);
    prep_kip_kernel<<<dim3(IPSEQ, NH), 128>>>(kip, kscale, kipn);

    // Fused dual-context attention
    const size_t smem = ATTN_SMEM_FLOATS * sizeof(float);
    cudaFuncSetAttribute(attn_kernel, cudaFuncAttributeMaxDynamicSharedMemorySize, (int)smem);
    attn_kernel<<<dim3(S_LEN / AQ, NH), blk, smem>>>(qr, qn, kr, v, kipn, vip, ao);

    // Output projection -> d_out
    gemm_nt_bias<<<g_big, blk>>>(ao, Wo, bo, (float*)d_out, S_LEN, HIDN, HIDN);
}

// round 4
// speedup vs baseline: 1.7674x; 1.7674x over previous
#include <cuda_runtime.h>
#include <cuda_bf16.h>
#include <cstdint>
#include <cstddef>

// ---------------------------------------------------------------------------
// Problem constants (FluxIPAttnProcessor: B=1, S=2048, H=24, D=128)
// ---------------------------------------------------------------------------
#define S_LEN 2048
#define HIDN  3072
#define NH    24
#define HD    128
#define IPSEQ 512
#define IPDIM 1152

#define DEV_INLINE __device__ __forceinline__

// ---------------------------------------------------------------------------
// PTX helpers: cp.async + ldmatrix + mma.sync (all baseline sm_80+, no "a")
// ---------------------------------------------------------------------------
#define CP_ASYNC16(smaddr, gptr) \
    asm volatile("cp.async.cg.shared.global [%0], [%1], 16;" :: "r"(smaddr), "l"(gptr) : "memory")
#define CP_ASYNC_COMMIT() asm volatile("cp.async.commit_group;" ::: "memory")
#define CP_ASYNC_WAIT(n)  asm volatile("cp.async.wait_group %0;" :: "n"(n) : "memory")

DEV_INLINE void ldsm_x4(uint32_t* r, uint32_t addr) {
    asm volatile("ldmatrix.sync.aligned.m8n8.x4.shared.b16 {%0,%1,%2,%3}, [%4];"
        : "=r"(r[0]), "=r"(r[1]), "=r"(r[2]), "=r"(r[3]) : "r"(addr));
}

DEV_INLINE void mma_bf16(float* d, const uint32_t* a, uint32_t b0, uint32_t b1) {
    asm volatile(
        "mma.sync.aligned.m16n8k16.row.col.f32.bf16.bf16.f32 "
        "{%0,%1,%2,%3}, {%4,%5,%6,%7}, {%8,%9}, {%0,%1,%2,%3};"
        : "+f"(d[0]), "+f"(d[1]), "+f"(d[2]), "+f"(d[3])
        : "r"(a[0]), "r"(a[1]), "r"(a[2]), "r"(a[3]), "r"(b0), "r"(b1));
}

// ---------------------------------------------------------------------------
// Packed fp32x2 helpers (SIMT attention)
// ---------------------------------------------------------------------------
DEV_INLINE unsigned long long pack2(float lo, float hi) {
    unsigned long long r;
    asm("mov.b64 %0, {%1, %2};"
        : "=l"(r) : "r"(__float_as_uint(lo)), "r"(__float_as_uint(hi)));
    return r;
}
DEV_INLINE void unpack2(unsigned long long v, float& lo, float& hi) {
    unsigned int a, b;
    asm("mov.b64 {%0, %1}, %2;" : "=r"(a), "=r"(b) : "l"(v));
    lo = __uint_as_float(a); hi = __uint_as_float(b);
}
DEV_INLINE void fma2(unsigned long long& d, unsigned long long a, unsigned long long b) {
    asm("fma.rn.f32x2 %0, %1, %2, %0;" : "+l"(d) : "l"(a), "l"(b));
}
DEV_INLINE void mul2(unsigned long long& d, unsigned long long a) {
    asm("mul.rn.f32x2 %0, %0, %1;" : "+l"(d) : "l"(a));
}

// ---------------------------------------------------------------------------
// Device scratch
// ---------------------------------------------------------------------------
__device__ float g_q   [S_LEN * HIDN];
__device__ float g_k   [S_LEN * HIDN];
__device__ float g_v   [S_LEN * HIDN];
__device__ float g_qr  [S_LEN * HIDN];
__device__ float g_qn  [S_LEN * HIDN];
__device__ float g_kr  [S_LEN * HIDN];
__device__ float g_kip [IPSEQ * HIDN];
__device__ float g_kipn[IPSEQ * HIDN];
__device__ float g_vip [IPSEQ * HIDN];
__device__ float g_ao  [S_LEN * HIDN];

__device__ __nv_bfloat16 g_hb_hi [S_LEN * HIDN];
__device__ __nv_bfloat16 g_hb_lo [S_LEN * HIDN];
__device__ __nv_bfloat16 g_wq_hi [HIDN * HIDN];
__device__ __nv_bfloat16 g_wq_lo [HIDN * HIDN];
__device__ __nv_bfloat16 g_wk_hi [HIDN * HIDN];
__device__ __nv_bfloat16 g_wk_lo [HIDN * HIDN];
__device__ __nv_bfloat16 g_wv_hi [HIDN * HIDN];
__device__ __nv_bfloat16 g_wv_lo [HIDN * HIDN];
__device__ __nv_bfloat16 g_wo_hi [HIDN * HIDN];
__device__ __nv_bfloat16 g_wo_lo [HIDN * HIDN];
__device__ __nv_bfloat16 g_wkip_hi[HIDN * IPDIM];
__device__ __nv_bfloat16 g_wkip_lo[HIDN * IPDIM];
__device__ __nv_bfloat16 g_wvip_hi[HIDN * IPDIM];
__device__ __nv_bfloat16 g_wvip_lo[HIDN * IPDIM];
__device__ __nv_bfloat16 g_ip_hi [IPSEQ * IPDIM];
__device__ __nv_bfloat16 g_ip_lo [IPSEQ * IPDIM];
__device__ __nv_bfloat16 g_ao_hi [S_LEN * HIDN];
__device__ __nv_bfloat16 g_ao_lo [S_LEN * HIDN];

// ---------------------------------------------------------------------------
// fp32 -> (bf16 hi, bf16 lo) split conversion, vectorized x4
// ---------------------------------------------------------------------------
__global__ void cvt_split(const float* __restrict__ x,
                          __nv_bfloat16* __restrict__ hi,
                          __nv_bfloat16* __restrict__ lo, int n4)
{
    int i = blockIdx.x * blockDim.x + threadIdx.x;
    if (i >= n4) return;
    float4 v = ((const float4*)x)[i];
    __nv_bfloat16 h0 = __float2bfloat16(v.x);
    __nv_bfloat16 h1 = __float2bfloat16(v.y);
    __nv_bfloat16 h2 = __float2bfloat16(v.z);
    __nv_bfloat16 h3 = __float2bfloat16(v.w);
    __nv_bfloat16 l0 = __float2bfloat16(v.x - __bfloat162float(h0));
    __nv_bfloat16 l1 = __float2bfloat16(v.y - __bfloat162float(h1));
    __nv_bfloat16 l2 = __float2bfloat16(v.z - __bfloat162float(h2));
    __nv_bfloat16 l3 = __float2bfloat16(v.w - __bfloat162float(h3));
    __nv_bfloat162 hp0; hp0.x = h0; hp0.y = h1;
    __nv_bfloat162 hp1; hp1.x = h2; hp1.y = h3;
    __nv_bfloat162 lp0; lp0.x = l0; lp0.y = l1;
    __nv_bfloat162 lp1; lp1.x = l2; lp1.y = l3;
    ((__nv_bfloat162*)hi)[2 * i]     = hp0;
    ((__nv_bfloat162*)hi)[2 * i + 1] = hp1;
    ((__nv_bfloat162*)lo)[2 * i]     = lp0;
    ((__nv_bfloat162*)lo)[2 * i + 1] = lp1;
}

// ---------------------------------------------------------------------------
// mma.sync split-bf16 GEMM: C[M,N] = A[M,K]*B[N,K]^T + bias[N]   (fp32 I/O)
// 3-term accumulation AhiBhi + AhiBlo + AloBhi in fp32 frags.
// CTA tile 128x128, 8 warps (4x2), warp tile 32x64, K-stage 64, dbl-buffered.
// Requires M%128==0, N%128==0, K%64==0 (all call sites comply).
// ---------------------------------------------------------------------------
#define KC 64
#define ROWB 144                       // 128B data + 16B pad
#define TILEB (128 * ROWB)             // 18432
#define STAGEB (4 * TILEB)             // 73728
#define GEMM_DSMEM (2 * STAGEB)        // 147456

__global__ void __launch_bounds__(256, 1) gemm_mma(
    const __nv_bfloat16* __restrict__ Ahi, const __nv_bfloat16* __restrict__ Alo,
    const __nv_bfloat16* __restrict__ Bhi, const __nv_bfloat16* __restrict__ Blo,
    const float* __restrict__ bias, float* __restrict__ C,
    int M, int N, int K)
{
    extern __shared__ __align__(128) char smem[];
    const uint32_t sbase = (uint32_t)__cvta_generic_to_shared(smem);
    const int tid  = threadIdx.x;
    const int lane = tid & 31;
    const int w    = tid >> 5;
    const int wm   = w >> 1;        // 0..3
    const int wn   = w & 1;         // 0..1
    const int m0   = blockIdx.y * 128;
    const int n0   = blockIdx.x * 128;

    auto load_stage = [&](int buf, int kt) {
        const int k0 = kt * KC;
        const uint32_t sb = sbase + buf * STAGEB;
#pragma unroll
        for (int op = 0; op < 4; op++) {
            const __nv_bfloat16* src = (op == 0) ? Ahi : (op == 1) ? Alo
                                      : (op == 2) ? Bhi : Blo;
            const int r0 = (op < 2) ? m0 : n0;
            const uint32_t so = sb + op * TILEB;
#pragma unroll
            for (int it = 0; it < 4; it++) {
                int idx = tid + it * 256;          // 0..1023
                int row = idx >> 3;
                int ch  = idx & 7;
                uint32_t sa = so + (uint32_t)(row * ROWB + ch * 16);
                const void* g = (const void*)(src + (size_t)(r0 + row) * K + k0 + ch * 8);
                CP_ASYNC16(sa, g);
            }
        }
        CP_ASYNC_COMMIT();
    };

    float c[2][8][4];
#pragma unroll
    for (int mt = 0; mt < 2; mt++)
#pragma unroll
        for (int nt = 0; nt < 8; nt++)
#pragma unroll
            for (int r = 0; r < 4; r++) c[mt][nt][r] = 0.0f;

    const int T = K / KC;
    load_stage(0, 0);
    if (T > 1) load_stage(1, 1);

#pragma unroll 1
    for (int i = 0; i < T; i++) {
        const int buf = i & 1;
        if (i + 1 < T) { CP_ASYNC_WAIT(1); } else { CP_ASYNC_WAIT(0); }
        __syncthreads();

        const uint32_t sb   = sbase + buf * STAGEB;
        const uint32_t sAhi = sb;
        const uint32_t sAlo = sb + TILEB;
        const uint32_t sBhi = sb + 2 * TILEB;
        const uint32_t sBlo = sb + 3 * TILEB;

#pragma unroll
        for (int ks = 0; ks < 4; ks++) {
            uint32_t ah[2][4], al[2][4], bh[4][4], bl[4][4];
#pragma unroll
            for (int mt = 0; mt < 2; mt++) {
                int row = wm * 32 + mt * 16 + (lane & 15);
                uint32_t off = (uint32_t)(row * ROWB + (lane >> 4) * 16 + ks * 32);
                ldsm_x4(ah[mt], sAhi + off);
                ldsm_x4(al[mt], sAlo + off);
            }
#pragma unroll
            for (int bq = 0; bq < 4; bq++) {
                int nrow = wn * 64 + bq * 16 + ((lane >> 4) << 3) + (lane & 7);
                uint32_t off = (uint32_t)(nrow * ROWB + ((lane >> 3) & 1) * 16 + ks * 32);
                ldsm_x4(bh[bq], sBhi + off);
                ldsm_x4(bl[bq], sBlo + off);
            }
#pragma unroll
            for (int mt = 0; mt < 2; mt++) {
#pragma unroll
                for (int bq = 0; bq < 4; bq++) {
                    mma_bf16(c[mt][2 * bq],     ah[mt], bh[bq][0], bh[bq][1]);
                    mma_bf16(c[mt][2 * bq + 1], ah[mt], bh[bq][2], bh[bq][3]);
                    mma_bf16(c[mt][2 * bq],     ah[mt], bl[bq][0], bl[bq][1]);
                    mma_bf16(c[mt][2 * bq + 1], ah[mt], bl[bq][2], bl[bq][3]);
                    mma_bf16(c[mt][2 * bq],     al[mt], bh[bq][0], bh[bq][1]);
                    mma_bf16(c[mt][2 * bq + 1], al[mt], bh[bq][2], bh[bq][3]);
                }
            }
        }
        __syncthreads();
        if (i + 2 < T) load_stage(buf, i + 2);
    }

    // Epilogue: add bias, store fp32
    const int crow  = wm * 32 + (lane >> 2);
    const int ccol0 = wn * 64 + (lane & 3) * 2;
#pragma unroll
    for (int mt = 0; mt < 2; mt++) {
#pragma unroll
        for (int nt = 0; nt < 8; nt++) {
            const int r  = m0 + crow + mt * 16;
            const int cc = n0 + ccol0 + nt * 8;
            const float b0v = bias[cc], b1v = bias[cc + 1];
            float* p  = C + (size_t)r * N + cc;
            float* p2 = p + 8 * N;
            p[0]  = c[mt][nt][0] + b0v;
            p[1]  = c[mt][nt][1] + b1v;
            p2[0] = c[mt][nt][2] + b0v;
            p2[1] = c[mt][nt][3] + b1v;
        }
    }
}

// ---------------------------------------------------------------------------
// Prep kernels: RoPE + RMSNorm
// ---------------------------------------------------------------------------
DEV_INLINE float blk_sumsq(float x, float* red, int d) {
    float v = x * x;
#pragma unroll
    for (int o = 16; o > 0; o >>= 1) v += __shfl_xor_sync(0xffffffffu, v, o);
    if ((d & 31) == 0) red[d >> 5] = v;
    __syncthreads();
    return red[0] + red[1] + red[2] + red[3];
}

__global__ void prep_q_kernel(const float* __restrict__ q,
                              const float* __restrict__ sinp, const float* __restrict__ cosp,
                              const float* __restrict__ qscale,
                              float* __restrict__ qrot, float* __restrict__ qnorm)
{
    __shared__ float red[4];
    const int s = blockIdx.x, hh = blockIdx.y, d = threadIdx.x;
    const size_t base = (size_t)s * HIDN + hh * HD;
    const float x = q[base + d];
    const float ss = blk_sumsq(x, red, d);
    const float rms = sqrtf(ss * (1.0f / 128.0f));
    const float inv = 1.0f / (rms + 1e-6f);
    qnorm[base + d] = qscale[d] * x * inv * 0.08838834764831845f;
    float outv;
    if (d < 64) {
        float rot = (d < 32) ? -q[base + d + 32] : q[base + d - 32];
        outv = x * cosp[s * 64 + d] + rot * sinp[s * 64 + d];
    } else {
        outv = x;
    }
    qrot[base + d] = outv;
}

__global__ void prep_k_kernel(const float* __restrict__ k,
                              const float* __restrict__ sinp, const float* __restrict__ cosp,
                              float* __restrict__ krot)
{
    const int s = blockIdx.x, hh = blockIdx.y, d = threadIdx.x;
    const size_t base = (size_t)s * HIDN + hh * HD;
    const float x = k[base + d];
    float outv;
    if (d < 64) {
        float rot = (d < 32) ? -k[base + d + 32] : k[base + d - 32];
        outv = x * cosp[s * 64 + d] + rot * sinp[s * 64 + d];
    } else {
        outv = x;
    }
    krot[base + d] = outv;
}

__global__ void prep_kip_kernel(const float* __restrict__ kip,
                                const float* __restrict__ kscale,
                                float* __restrict__ kipn)
{
    __shared__ float red[4];
    const int s = blockIdx.x, hh = blockIdx.y, d = threadIdx.x;
    const size_t base = (size_t)s * HIDN + hh * HD;
    const float x = kip[base + d];
    const float ss = blk_sumsq(x, red, d);
    const float rms = sqrtf(ss * (1.0f / 128.0f));
    const float inv = 1.0f / (rms + 1e-6f);
    kipn[base + d] = kscale[d] * x * inv * 0.08838834764831845f;
}

// ---------------------------------------------------------------------------
// Fused two-context flash attention (SIMT FFMA2, unchanged: known good)
// ---------------------------------------------------------------------------
#define AQ 128
#define AK 64
#define QT_STRIDE 129
#define KT_STRIDE 65
#define ATTN_SMEM_FLOATS (128 * QT_STRIDE + 128 * KT_STRIDE + AK * 128 + AQ * AK)

__global__ void __launch_bounds__(256, 1) attn_kernel(
    const float* __restrict__ qr,   const float* __restrict__ qn,
    const float* __restrict__ kr,   const float* __restrict__ vv,
    const float* __restrict__ kipn, const float* __restrict__ vip,
    float* __restrict__ out)
{
    extern __shared__ float sm[];
    float* Qt = sm;
    float* Kt = Qt + 128 * QT_STRIDE;
    float* Vs = Kt + 128 * KT_STRIDE;
    float* Ps = Vs + AK * 128;

    const int h    = blockIdx.y;
    const int q0   = blockIdx.x * AQ;
    const int tid  = threadIdx.x;
    const int ty   = tid >> 4;
    const int tx   = tid & 15;
    const int hofs = h * HD;

#pragma unroll 1
    for (int pass = 0; pass < 2; pass++) {
        const float* Qsrc = pass ? qn   : qr;
        const float* Ksrc = pass ? kipn : kr;
        const float* Vsrc = pass ? vip  : vv;
        const int nk = pass ? IPSEQ : S_LEN;

        __syncthreads();
#pragma unroll
        for (int it = 0; it < 16; it++) {
            int f  = tid + it * 256;
            int r  = f >> 5;
            int d4 = (f & 31) * 4;
            float4 q4 = *(const float4*)&Qsrc[(size_t)(q0 + r) * HIDN + hofs + d4];
            Qt[(d4 + 0) * QT_STRIDE + r] = q4.x;
            Qt[(d4 + 1) * QT_STRIDE + r] = q4.y;
            Qt[(d4 + 2) * QT_STRIDE + r] = q4.z;
            Qt[(d4 + 3) * QT_STRIDE + r] = q4.w;
        }

        float mrow[8], lrow[8];
        unsigned long long o[8][4];
#pragma unroll
        for (int i = 0; i < 8; i++) {
            mrow[i] = -1e30f; lrow[i] = 0.0f;
#pragma unroll
            for (int jp = 0; jp < 4; jp++) o[i][jp] = 0ull;
        }

#pragma unroll 1
        for (int kt = 0; kt < nk; kt += AK) {
            __syncthreads();
#pragma unroll
            for (int it = 0; it < 8; it++) {
                int f  = tid + it * 256;
                int cc = f >> 5;
                int d4 = (f & 31) * 4;
                float4 k4 = *(const float4*)&Ksrc[(size_t)(kt + cc) * HIDN + hofs + d4];
                Kt[(d4 + 0) * KT_STRIDE + cc] = k4.x;
                Kt[(d4 + 1) * KT_STRIDE + cc] = k4.y;
                Kt[(d4 + 2) * KT_STRIDE + cc] = k4.z;
                Kt[(d4 + 3) * KT_STRIDE + cc] = k4.w;
            }
#pragma unroll
            for (int it = 0; it < 8; it++) {
                int f  = tid + it * 256;
                int r  = f >> 5;
                int c4 = (f & 31) * 4;
                *(float4*)&Vs[r * 128 + c4] =
                    *(const float4*)&Vsrc[(size_t)(kt + r) * HIDN + hofs + c4];
            }
            __syncthreads();

            unsigned long long sp[8][2];
#pragma unroll
            for (int i = 0; i < 8; i++) { sp[i][0] = 0ull; sp[i][1] = 0ull; }
#pragma unroll 4
            for (int d = 0; d < 128; d++) {
                const float* qrow = &Qt[d * QT_STRIDE + ty * 8];
                const float* krow = &Kt[d * KT_STRIDE + tx * 4];
                unsigned long long kp0 = pack2(krow[0], krow[1]);
                unsigned long long kp1 = pack2(krow[2], krow[3]);
#pragma unroll
                for (int i = 0; i < 8; i++) {
                    unsigned long long qd = pack2(qrow[i], qrow[i]);
                    fma2(sp[i][0], qd, kp0);
                    fma2(sp[i][1], qd, kp1);
                }
            }

#pragma unroll
            for (int i = 0; i < 8; i++) {
                float s0, s1, s2, s3;
                unpack2(sp[i][0], s0, s1);
                unpack2(sp[i][1], s2, s3);
                float mx = fmaxf(fmaxf(s0, s1), fmaxf(s2, s3));
#pragma unroll
                for (int msk = 1; msk < 16; msk <<= 1)
                    mx = fmaxf(mx, __shfl_xor_sync(0xffffffffu, mx, msk));
                const float mn = fmaxf(mrow[i], mx);
                const float alpha = __expf(mrow[i] - mn);
                const float p0 = __expf(s0 - mn);
                const float p1 = __expf(s1 - mn);
                const float p2 = __expf(s2 - mn);
                const float p3 = __expf(s3 - mn);
                float rs = (p0 + p1) + (p2 + p3);
#pragma unroll
                for (int msk = 1; msk < 16; msk <<= 1)
                    rs += __shfl_xor_sync(0xffffffffu, rs, msk);
                lrow[i] = lrow[i] * alpha + rs;
                mrow[i] = mn;
                unsigned long long ad = pack2(alpha, alpha);
#pragma unroll
                for (int jp = 0; jp < 4; jp++) mul2(o[i][jp], ad);
                *(float4*)&Ps[(ty * 8 + i) * AK + tx * 4] = make_float4(p0, p1, p2, p3);
            }
            __syncthreads();

#pragma unroll 2
            for (int k = 0; k < AK; k++) {
                unsigned long long vp[4];
#pragma unroll
                for (int jp = 0; jp < 4; jp++)
                    vp[jp] = *(const unsigned long long*)&Vs[k * 128 + tx * 8 + jp * 2];
#pragma unroll
                for (int i = 0; i < 8; i++) {
                    const float p = Ps[(ty * 8 + i) * AK + k];
                    unsigned long long pd = pack2(p, p);
#pragma unroll
                    for (int jp = 0; jp < 4; jp++) fma2(o[i][jp], pd, vp[jp]);
                }
            }
        }

#pragma unroll
        for (int i = 0; i < 8; i++) {
            const float invl = 1.0f / lrow[i];
            float ov[8];
#pragma unroll
            for (int jp = 0; jp < 4; jp++) unpack2(o[i][jp], ov[2 * jp], ov[2 * jp + 1]);
#pragma unroll
            for (int j = 0; j < 8; j++) ov[j] *= invl;
            float* op = out + (size_t)(q0 + ty * 8 + i) * HIDN + hofs + tx * 8;
            if (pass == 0) {
                *(float4*)(op)     = make_float4(ov[0], ov[1], ov[2], ov[3]);
                *(float4*)(op + 4) = make_float4(ov[4], ov[5], ov[6], ov[7]);
            } else {
                float4 e0 = *(float4*)(op);
                float4 e1 = *(float4*)(op + 4);
                e0.x += ov[0]; e0.y += ov[1]; e0.z += ov[2]; e0.w += ov[3];
                e1.x += ov[4]; e1.y += ov[5]; e1.z += ov[6]; e1.w += ov[7];
                *(float4*)(op)     = e0;
                *(float4*)(op + 4) = e1;
            }
        }
    }
}

// ---------------------------------------------------------------------------
// Launch
// ---------------------------------------------------------------------------
extern "C" void kernel_launch(void* const* d_in, const int* in_sizes, int n_in,
                              void* d_out, int out_size)
{
    const float* hidden = (const float*)d_in[0];
    const float* iph    = (const float*)d_in[1];
    const float* sinp   = (const float*)d_in[2];
    const float* cosp   = (const float*)d_in[3];
    const float* Wq     = (const float*)d_in[4];
    const float* bq     = (const float*)d_in[5];
    const float* Wk     = (const float*)d_in[6];
    const float* bk     = (const float*)d_in[7];
    const float* Wv     = (const float*)d_in[8];
    const float* bv     = (const float*)d_in[9];
    const float* Wo     = (const float*)d_in[10];
    const float* bo     = (const float*)d_in[11];
    const float* Wk_ip  = (const float*)d_in[12];
    const float* bk_ip  = (const float*)d_in[13];
    const float* Wv_ip  = (const float*)d_in[14];
    const float* bv_ip  = (const float*)d_in[15];
    const float* qscale = (const float*)d_in[16];
    const float* kscale = (const float*)d_in[17];

    float *q, *k, *v, *qr, *qn, *kr, *kip, *kipn, *vip, *ao;
    cudaGetSymbolAddress((void**)&q,    g_q);
    cudaGetSymbolAddress((void**)&k,    g_k);
    cudaGetSymbolAddress((void**)&v,    g_v);
    cudaGetSymbolAddress((void**)&qr,   g_qr);
    cudaGetSymbolAddress((void**)&qn,   g_qn);
    cudaGetSymbolAddress((void**)&kr,   g_kr);
    cudaGetSymbolAddress((void**)&kip,  g_kip);
    cudaGetSymbolAddress((void**)&kipn, g_kipn);
    cudaGetSymbolAddress((void**)&vip,  g_vip);
    cudaGetSymbolAddress((void**)&ao,   g_ao);

    __nv_bfloat16 *hb_hi, *hb_lo, *wq_hi, *wq_lo, *wk_hi, *wk_lo, *wv_hi, *wv_lo,
                  *wo_hi, *wo_lo, *wkip_hi, *wkip_lo, *wvip_hi, *wvip_lo,
                  *ip_hi, *ip_lo, *ao_hi, *ao_lo;
    cudaGetSymbolAddress((void**)&hb_hi,   g_hb_hi);
    cudaGetSymbolAddress((void**)&hb_lo,   g_hb_lo);
    cudaGetSymbolAddress((void**)&wq_hi,   g_wq_hi);
    cudaGetSymbolAddress((void**)&wq_lo,   g_wq_lo);
    cudaGetSymbolAddress((void**)&wk_hi,   g_wk_hi);
    cudaGetSymbolAddress((void**)&wk_lo,   g_wk_lo);
    cudaGetSymbolAddress((void**)&wv_hi,   g_wv_hi);
    cudaGetSymbolAddress((void**)&wv_lo,   g_wv_lo);
    cudaGetSymbolAddress((void**)&wo_hi,   g_wo_hi);
    cudaGetSymbolAddress((void**)&wo_lo,   g_wo_lo);
    cudaGetSymbolAddress((void**)&wkip_hi, g_wkip_hi);
    cudaGetSymbolAddress((void**)&wkip_lo, g_wkip_lo);
    cudaGetSymbolAddress((void**)&wvip_hi, g_wvip_hi);
    cudaGetSymbolAddress((void**)&wvip_lo, g_wvip_lo);
    cudaGetSymbolAddress((void**)&ip_hi,   g_ip_hi);
    cudaGetSymbolAddress((void**)&ip_lo,   g_ip_lo);
    cudaGetSymbolAddress((void**)&ao_hi,   g_ao_hi);
    cudaGetSymbolAddress((void**)&ao_lo,   g_ao_lo);

    auto cvt = [&](const float* src, __nv_bfloat16* hi, __nv_bfloat16* lo, int n) {
        int n4 = n / 4;
        cvt_split<<<(n4 + 255) / 256, 256>>>(src, hi, lo, n4);
    };
    cvt(hidden, hb_hi, hb_lo, S_LEN * HIDN);
    cvt(Wq, wq_hi, wq_lo, HIDN * HIDN);
    cvt(Wk, wk_hi, wk_lo, HIDN * HIDN);
    cvt(Wv, wv_hi, wv_lo, HIDN * HIDN);
    cvt(Wo, wo_hi, wo_lo, HIDN * HIDN);
    cvt(Wk_ip, wkip_hi, wkip_lo, HIDN * IPDIM);
    cvt(Wv_ip, wvip_hi, wvip_lo, HIDN * IPDIM);
    cvt(iph, ip_hi, ip_lo, IPSEQ * IPDIM);

    cudaFuncSetAttribute(gemm_mma, cudaFuncAttributeMaxDynamicSharedMemorySize, GEMM_DSMEM);

    const dim3 g_big(HIDN / 128, S_LEN / 128);   // (24, 16)
    const dim3 g_ip (HIDN / 128, IPSEQ / 128);   // (24, 4)

    gemm_mma<<<g_big, 256, GEMM_DSMEM>>>(hb_hi, hb_lo, wq_hi, wq_lo, bq, q, S_LEN, HIDN, HIDN);
    gemm_mma<<<g_big, 256, GEMM_DSMEM>>>(hb_hi, hb_lo, wk_hi, wk_lo, bk, k, S_LEN, HIDN, HIDN);
    gemm_mma<<<g_big, 256, GEMM_DSMEM>>>(hb_hi, hb_lo, wv_hi, wv_lo, bv, v, S_LEN, HIDN, HIDN);
    gemm_mma<<<g_ip,  256, GEMM_DSMEM>>>(ip_hi, ip_lo, wkip_hi, wkip_lo, bk_ip, kip, IPSEQ, HIDN, IPDIM);
    gemm_mma<<<g_ip,  256, GEMM_DSMEM>>>(ip_hi, ip_lo, wvip_hi, wvip_lo, bv_ip, vip, IPSEQ, HIDN, IPDIM);

    prep_q_kernel  <<<dim3(S_LEN, NH), 128>>>(q, sinp, cosp, qscale, qr, qn);
    prep_k_kernel  <<<dim3(S_LEN, NH), 128>>>(k, sinp, cosp, kr);
    prep_kip_kernel<<<dim3(IPSEQ, NH), 128>>>(kip, kscale, kipn);

    const size_t smem = ATTN_SMEM_FLOATS * sizeof(float);
    cudaFuncSetAttribute(attn_kernel, cudaFuncAttributeMaxDynamicSharedMemorySize, (int)smem);
    attn_kernel<<<dim3(S_LEN / AQ, NH), 256, smem>>>(qr, qn, kr, v, kipn, vip, ao);

    cvt(ao, ao_hi, ao_lo, S_LEN * HIDN);
    gemm_mma<<<g_big, 256, GEMM_DSMEM>>>(ao_hi, ao_lo, wo_hi, wo_lo, bo, (float*)d_out, S_LEN, HIDN, HIDN);
}

// round 5
// speedup vs baseline: 2.9738x; 1.6825x over previous
#include <cuda_runtime.h>
#include <cuda_bf16.h>
#include <cuda_fp16.h>
#include <cstdint>
#include <cstddef>

// ---------------------------------------------------------------------------
// Problem constants (FluxIPAttnProcessor: B=1, S=2048, H=24, D=128)
// ---------------------------------------------------------------------------
#define S_LEN 2048
#define HIDN  3072
#define NH    24
#define HD    128
#define IPSEQ 512
#define IPDIM 1152

#define DEV_INLINE __device__ __forceinline__

// ---------------------------------------------------------------------------
// PTX helpers: cp.async + ldmatrix + mma.sync (baseline sm_80+ PTX only)
// ---------------------------------------------------------------------------
#define CP_ASYNC16(smaddr, gptr) \
    asm volatile("cp.async.cg.shared.global [%0], [%1], 16;" :: "r"(smaddr), "l"(gptr) : "memory")
#define CP_ASYNC_COMMIT() asm volatile("cp.async.commit_group;" ::: "memory")
#define CP_ASYNC_WAIT(n)  asm volatile("cp.async.wait_group %0;" :: "n"(n) : "memory")

DEV_INLINE void ldsm_x4(uint32_t* r, uint32_t addr) {
    asm volatile("ldmatrix.sync.aligned.m8n8.x4.shared.b16 {%0,%1,%2,%3}, [%4];"
        : "=r"(r[0]), "=r"(r[1]), "=r"(r[2]), "=r"(r[3]) : "r"(addr));
}

DEV_INLINE void mma_bf16(float* d, const uint32_t* a, uint32_t b0, uint32_t b1) {
    asm volatile(
        "mma.sync.aligned.m16n8k16.row.col.f32.bf16.bf16.f32 "
        "{%0,%1,%2,%3}, {%4,%5,%6,%7}, {%8,%9}, {%0,%1,%2,%3};"
        : "+f"(d[0]), "+f"(d[1]), "+f"(d[2]), "+f"(d[3])
        : "r"(a[0]), "r"(a[1]), "r"(a[2]), "r"(a[3]), "r"(b0), "r"(b1));
}

DEV_INLINE void mma_f16(float* d, const uint32_t* a, uint32_t b0, uint32_t b1) {
    asm volatile(
        "mma.sync.aligned.m16n8k16.row.col.f32.f16.f16.f32 "
        "{%0,%1,%2,%3}, {%4,%5,%6,%7}, {%8,%9}, {%0,%1,%2,%3};"
        : "+f"(d[0]), "+f"(d[1]), "+f"(d[2]), "+f"(d[3])
        : "r"(a[0]), "r"(a[1]), "r"(a[2]), "r"(a[3]), "r"(b0), "r"(b1));
}

// pack two f32 -> f16x2 register (lo = first arg, hi = second arg)
DEV_INLINE uint32_t packf16(float lo, float hi) {
    uint32_t r;
    asm("cvt.rn.f16x2.f32 %0, %1, %2;" : "=r"(r) : "f"(hi), "f"(lo));
    return r;
}

// ---------------------------------------------------------------------------
// Device scratch
// ---------------------------------------------------------------------------
__device__ float g_q   [S_LEN * HIDN];
__device__ float g_k   [S_LEN * HIDN];
__device__ float g_v   [S_LEN * HIDN];
__device__ float g_kip [IPSEQ * HIDN];
__device__ float g_vip [IPSEQ * HIDN];
__device__ float g_ao  [S_LEN * HIDN];

__device__ __nv_bfloat16 g_hb_hi [S_LEN * HIDN];
__device__ __nv_bfloat16 g_hb_lo [S_LEN * HIDN];
__device__ __nv_bfloat16 g_wq_hi [HIDN * HIDN];
__device__ __nv_bfloat16 g_wq_lo [HIDN * HIDN];
__device__ __nv_bfloat16 g_wk_hi [HIDN * HIDN];
__device__ __nv_bfloat16 g_wk_lo [HIDN * HIDN];
__device__ __nv_bfloat16 g_wv_hi [HIDN * HIDN];
__device__ __nv_bfloat16 g_wv_lo [HIDN * HIDN];
__device__ __nv_bfloat16 g_wo_hi [HIDN * HIDN];
__device__ __nv_bfloat16 g_wo_lo [HIDN * HIDN];
__device__ __nv_bfloat16 g_wkip_hi[HIDN * IPDIM];
__device__ __nv_bfloat16 g_wkip_lo[HIDN * IPDIM];
__device__ __nv_bfloat16 g_wvip_hi[HIDN * IPDIM];
__device__ __nv_bfloat16 g_wvip_lo[HIDN * IPDIM];
__device__ __nv_bfloat16 g_ip_hi [IPSEQ * IPDIM];
__device__ __nv_bfloat16 g_ip_lo [IPSEQ * IPDIM];
__device__ __nv_bfloat16 g_ao_hi [S_LEN * HIDN];
__device__ __nv_bfloat16 g_ao_lo [S_LEN * HIDN];

// attention operands (bf16 hi/lo) + fp16 transposed V
__device__ __nv_bfloat16 g_qr_hi [S_LEN * HIDN];
__device__ __nv_bfloat16 g_qr_lo [S_LEN * HIDN];
__device__ __nv_bfloat16 g_qn_hi [S_LEN * HIDN];
__device__ __nv_bfloat16 g_qn_lo [S_LEN * HIDN];
__device__ __nv_bfloat16 g_kr_hi [S_LEN * HIDN];
__device__ __nv_bfloat16 g_kr_lo [S_LEN * HIDN];
__device__ __nv_bfloat16 g_kipn_hi[IPSEQ * HIDN];
__device__ __nv_bfloat16 g_kipn_lo[IPSEQ * HIDN];
__device__ __half g_vt  [NH * HD * S_LEN];
__device__ __half g_vipt[NH * HD * IPSEQ];

// ---------------------------------------------------------------------------
// fp32 -> (bf16 hi, bf16 lo) split conversion, vectorized x4
// ---------------------------------------------------------------------------
__global__ void cvt_split(const float* __restrict__ x,
                          __nv_bfloat16* __restrict__ hi,
                          __nv_bfloat16* __restrict__ lo, int n4)
{
    int i = blockIdx.x * blockDim.x + threadIdx.x;
    if (i >= n4) return;
    float4 v = ((const float4*)x)[i];
    __nv_bfloat16 h0 = __float2bfloat16(v.x);
    __nv_bfloat16 h1 = __float2bfloat16(v.y);
    __nv_bfloat16 h2 = __float2bfloat16(v.z);
    __nv_bfloat16 h3 = __float2bfloat16(v.w);
    __nv_bfloat16 l0 = __float2bfloat16(v.x - __bfloat162float(h0));
    __nv_bfloat16 l1 = __float2bfloat16(v.y - __bfloat162float(h1));
    __nv_bfloat16 l2 = __float2bfloat16(v.z - __bfloat162float(h2));
    __nv_bfloat16 l3 = __float2bfloat16(v.w - __bfloat162float(h3));
    __nv_bfloat162 hp0; hp0.x = h0; hp0.y = h1;
    __nv_bfloat162 hp1; hp1.x = h2; hp1.y = h3;
    __nv_bfloat162 lp0; lp0.x = l0; lp0.y = l1;
    __nv_bfloat162 lp1; lp1.x = l2; lp1.y = l3;
    ((__nv_bfloat162*)hi)[2 * i]     = hp0;
    ((__nv_bfloat162*)hi)[2 * i + 1] = hp1;
    ((__nv_bfloat162*)lo)[2 * i]     = lp0;
    ((__nv_bfloat162*)lo)[2 * i + 1] = lp1;
}

// ---------------------------------------------------------------------------
// transpose V: fp32 [s][h*HD+d] -> fp16 vt[(h*HD+d)*seqlen + s]
// ---------------------------------------------------------------------------
__global__ void transpose_half(const float* __restrict__ v, __half* __restrict__ vt,
                               int seqlen)
{
    __shared__ float t[32][33];
    const int s0 = blockIdx.x * 32, d0 = blockIdx.y * 32, h = blockIdx.z;
    const int tx = threadIdx.x & 31, ty = threadIdx.x >> 5;
#pragma unroll
    for (int i = 0; i < 4; i++) {
        int row = ty + i * 8;
        t[row][tx] = v[(size_t)(s0 + row) * HIDN + h * HD + d0 + tx];
    }
    __syncthreads();
#pragma unroll
    for (int i = 0; i < 4; i++) {
        int d = ty + i * 8;
        vt[(size_t)(h * HD + d0 + d) * seqlen + s0 + tx] = __float2half(t[tx][d]);
    }
}

// ---------------------------------------------------------------------------
// mma.sync split-bf16 GEMM (3-stage cp.async pipeline)
// C[M,N] = A[M,K]*B[N,K]^T + bias[N]   (fp32 I/O)
// ---------------------------------------------------------------------------
#define KC 64
#define ROWB 144
#define TILEB (128 * ROWB)             // 18432
#define STAGEB (4 * TILEB)             // 73728
#define GEMM_DSMEM (3 * STAGEB)        // 221184

__global__ void __launch_bounds__(256, 1) gemm_mma(
    const __nv_bfloat16* __restrict__ Ahi, const __nv_bfloat16* __restrict__ Alo,
    const __nv_bfloat16* __restrict__ Bhi, const __nv_bfloat16* __restrict__ Blo,
    const float* __restrict__ bias, float* __restrict__ C,
    int M, int N, int K)
{
    extern __shared__ __align__(128) char smem[];
    const uint32_t sbase = (uint32_t)__cvta_generic_to_shared(smem);
    const int tid  = threadIdx.x;
    const int lane = tid & 31;
    const int w    = tid >> 5;
    const int wm   = w >> 1;
    const int wn   = w & 1;
    const int m0   = blockIdx.y * 128;
    const int n0   = blockIdx.x * 128;

    auto load_stage = [&](int buf, int kt) {
        const int k0 = kt * KC;
        const uint32_t sb = sbase + buf * STAGEB;
#pragma unroll
        for (int op = 0; op < 4; op++) {
            const __nv_bfloat16* src = (op == 0) ? Ahi : (op == 1) ? Alo
                                      : (op == 2) ? Bhi : Blo;
            const int r0 = (op < 2) ? m0 : n0;
            const uint32_t so = sb + op * TILEB;
#pragma unroll
            for (int it = 0; it < 4; it++) {
                int idx = tid + it * 256;
                int row = idx >> 3;
                int ch  = idx & 7;
                uint32_t sa = so + (uint32_t)(row * ROWB + ch * 16);
                const void* g = (const void*)(src + (size_t)(r0 + row) * K + k0 + ch * 8);
                CP_ASYNC16(sa, g);
            }
        }
        CP_ASYNC_COMMIT();
    };

    float c[2][8][4];
#pragma unroll
    for (int mt = 0; mt < 2; mt++)
#pragma unroll
        for (int nt = 0; nt < 8; nt++)
#pragma unroll
            for (int r = 0; r < 4; r++) c[mt][nt][r] = 0.0f;

    const int T = K / KC;
    load_stage(0, 0);
    if (T > 1) load_stage(1, 1);

    int buf = 0;
#pragma unroll 1
    for (int i = 0; i < T; i++) {
        if (i + 1 < T) { CP_ASYNC_WAIT(1); } else { CP_ASYNC_WAIT(0); }
        __syncthreads();
        if (i + 2 < T) {
            int nb = buf + 2; if (nb >= 3) nb -= 3;
            load_stage(nb, i + 2);
        }

        const uint32_t sb   = sbase + buf * STAGEB;
        const uint32_t sAhi = sb;
        const uint32_t sAlo = sb + TILEB;
        const uint32_t sBhi = sb + 2 * TILEB;
        const uint32_t sBlo = sb + 3 * TILEB;

#pragma unroll
        for (int ks = 0; ks < 4; ks++) {
            uint32_t ah[2][4], al[2][4], bh[4][4], bl[4][4];
#pragma unroll
            for (int mt = 0; mt < 2; mt++) {
                int row = wm * 32 + mt * 16 + (lane & 15);
                uint32_t off = (uint32_t)(row * ROWB + (lane >> 4) * 16 + ks * 32);
                ldsm_x4(ah[mt], sAhi + off);
                ldsm_x4(al[mt], sAlo + off);
            }
#pragma unroll
            for (int bq = 0; bq < 4; bq++) {
                int nrow = wn * 64 + bq * 16 + ((lane >> 4) << 3) + (lane & 7);
                uint32_t off = (uint32_t)(nrow * ROWB + ((lane >> 3) & 1) * 16 + ks * 32);
                ldsm_x4(bh[bq], sBhi + off);
                ldsm_x4(bl[bq], sBlo + off);
            }
#pragma unroll
            for (int mt = 0; mt < 2; mt++) {
#pragma unroll
                for (int bq = 0; bq < 4; bq++) {
                    mma_bf16(c[mt][2 * bq],     ah[mt], bh[bq][0], bh[bq][1]);
                    mma_bf16(c[mt][2 * bq + 1], ah[mt], bh[bq][2], bh[bq][3]);
                    mma_bf16(c[mt][2 * bq],     ah[mt], bl[bq][0], bl[bq][1]);
                    mma_bf16(c[mt][2 * bq + 1], ah[mt], bl[bq][2], bl[bq][3]);
                    mma_bf16(c[mt][2 * bq],     al[mt], bh[bq][0], bh[bq][1]);
                    mma_bf16(c[mt][2 * bq + 1], al[mt], bh[bq][2], bh[bq][3]);
                }
            }
        }
        __syncthreads();
        buf = (buf + 1 == 3) ? 0 : buf + 1;
    }

    const int crow  = wm * 32 + (lane >> 2);
    const int ccol0 = wn * 64 + (lane & 3) * 2;
#pragma unroll
    for (int mt = 0; mt < 2; mt++) {
#pragma unroll
        for (int nt = 0; nt < 8; nt++) {
            const int r  = m0 + crow + mt * 16;
            const int cc = n0 + ccol0 + nt * 8;
            const float b0v = bias[cc], b1v = bias[cc + 1];
            float* p  = C + (size_t)r * N + cc;
            float* p2 = p + 8 * N;
            p[0]  = c[mt][nt][0] + b0v;
            p[1]  = c[mt][nt][1] + b1v;
            p2[0] = c[mt][nt][2] + b0v;
            p2[1] = c[mt][nt][3] + b1v;
        }
    }
}

// ---------------------------------------------------------------------------
// Prep kernels: RoPE + RMSNorm, writing split bf16 outputs
// ---------------------------------------------------------------------------
DEV_INLINE float blk_sumsq(float x, float* red, int d) {
    float v = x * x;
#pragma unroll
    for (int o = 16; o > 0; o >>= 1) v += __shfl_xor_sync(0xffffffffu, v, o);
    if ((d & 31) == 0) red[d >> 5] = v;
    __syncthreads();
    return red[0] + red[1] + red[2] + red[3];
}

DEV_INLINE void split_store(__nv_bfloat16* hi, __nv_bfloat16* lo, size_t idx, float x) {
    __nv_bfloat16 h = __float2bfloat16(x);
    hi[idx] = h;
    lo[idx] = __float2bfloat16(x - __bfloat162float(h));
}

__global__ void prep_q_kernel(const float* __restrict__ q,
                              const float* __restrict__ sinp, const float* __restrict__ cosp,
                              const float* __restrict__ qscale,
                              __nv_bfloat16* __restrict__ qr_hi, __nv_bfloat16* __restrict__ qr_lo,
                              __nv_bfloat16* __restrict__ qn_hi, __nv_bfloat16* __restrict__ qn_lo)
{
    __shared__ float red[4];
    const int s = blockIdx.x, hh = blockIdx.y, d = threadIdx.x;
    const size_t base = (size_t)s * HIDN + hh * HD;
    const float x = q[base + d];
    const float ss = blk_sumsq(x, red, d);
    const float rms = sqrtf(ss * (1.0f / 128.0f));
    const float inv = 1.0f / (rms + 1e-6f);
    split_store(qn_hi, qn_lo, base + d, qscale[d] * x * inv * 0.08838834764831845f);
    float outv;
    if (d < 64) {
        float rot = (d < 32) ? -q[base + d + 32] : q[base + d - 32];
        outv = x * cosp[s * 64 + d] + rot * sinp[s * 64 + d];
    } else {
        outv = x;
    }
    split_store(qr_hi, qr_lo, base + d, outv);
}

__global__ void prep_k_kernel(const float* __restrict__ k,
                              const float* __restrict__ sinp, const float* __restrict__ cosp,
                              __nv_bfloat16* __restrict__ kr_hi, __nv_bfloat16* __restrict__ kr_lo)
{
    const int s = blockIdx.x, hh = blockIdx.y, d = threadIdx.x;
    const size_t base = (size_t)s * HIDN + hh * HD;
    const float x = k[base + d];
    float outv;
    if (d < 64) {
        float rot = (d < 32) ? -k[base + d + 32] : k[base + d - 32];
        outv = x * cosp[s * 64 + d] + rot * sinp[s * 64 + d];
    } else {
        outv = x;
    }
    split_store(kr_hi, kr_lo, base + d, outv);
}

__global__ void prep_kip_kernel(const float* __restrict__ kip,
                                const float* __restrict__ kscale,
                                __nv_bfloat16* __restrict__ kn_hi, __nv_bfloat16* __restrict__ kn_lo)
{
    __shared__ float red[4];
    const int s = blockIdx.x, hh = blockIdx.y, d = threadIdx.x;
    const size_t base = (size_t)s * HIDN + hh * HD;
    const float x = kip[base + d];
    const float ss = blk_sumsq(x, red, d);
    const float rms = sqrtf(ss * (1.0f / 128.0f));
    const float inv = 1.0f / (rms + 1e-6f);
    split_store(kn_hi, kn_lo, base + d, kscale[d] * x * inv * 0.08838834764831845f);
}

// ---------------------------------------------------------------------------
// mma.sync fused two-context flash attention.
// Grid (S/128, NH), 256 threads (8 warps). Warp = 16 q-rows x 64 keys.
// S = QK^T: split-bf16 3-term; softmax fp32 in regs; P*V: fp16 single-term.
// K/V double-buffered cp.async; V pre-transposed (vt[h][d][s], fp16).
// ---------------------------------------------------------------------------
#define QROWB 272
#define KROWB 272
#define VROWB 144
#define QTILE (128 * QROWB)            // 34816
#define KTILE (64 * KROWB)             // 17408
#define VTILE (128 * VROWB)            // 18432
#define ATT_STAGE (2 * KTILE + VTILE)  // 53248
#define ATT_SMEM (2 * QTILE + 2 * ATT_STAGE)  // 176128

__global__ void __launch_bounds__(256, 1) attn_mma(
    const __nv_bfloat16* __restrict__ qr_hi, const __nv_bfloat16* __restrict__ qr_lo,
    const __nv_bfloat16* __restrict__ qn_hi, const __nv_bfloat16* __restrict__ qn_lo,
    const __nv_bfloat16* __restrict__ kr_hi, const __nv_bfloat16* __restrict__ kr_lo,
    const __nv_bfloat16* __restrict__ kip_hi, const __nv_bfloat16* __restrict__ kip_lo,
    const __half* __restrict__ vtp, const __half* __restrict__ viptp,
    float* __restrict__ out)
{
    extern __shared__ __align__(128) char smem[];
    const uint32_t sb  = (uint32_t)__cvta_generic_to_shared(smem);
    const uint32_t sQh = sb, sQl = sb + QTILE;
    const uint32_t sSt = sb + 2 * QTILE;

    const int h = blockIdx.y, q0 = blockIdx.x * 128, hofs = h * HD;
    const int tid = threadIdx.x, lane = tid & 31, w = tid >> 5;

    // per-lane ldmatrix offsets (A/B matrices x4 addressing)
    const uint32_t lrowq = (uint32_t)((w * 16 + (lane & 15)) * QROWB + (lane >> 4) * 16);
    const uint32_t lrowk = (uint32_t)((lane & 15) * KROWB + (lane >> 4) * 16);
    const uint32_t lrowv = (uint32_t)((lane & 15) * VROWB + (lane >> 4) * 16);

#pragma unroll 1
    for (int pass = 0; pass < 2; pass++) {
        const __nv_bfloat16* Qh = pass ? qn_hi  : qr_hi;
        const __nv_bfloat16* Ql = pass ? qn_lo  : qr_lo;
        const __nv_bfloat16* Kh = pass ? kip_hi : kr_hi;
        const __nv_bfloat16* Kl = pass ? kip_lo : kr_lo;
        const __half* Vt = pass ? viptp : vtp;
        const int nk = pass ? IPSEQ : S_LEN;
        const int ntiles = nk >> 6;

        __syncthreads();
        // Q hi+lo: 128 rows x 16 chunks each
#pragma unroll
        for (int it = 0; it < 8; it++) {
            int idx = tid + it * 256;
            int row = idx >> 4, ch = idx & 15;
            const size_t g = (size_t)(q0 + row) * HIDN + hofs + ch * 8;
            CP_ASYNC16(sQh + (uint32_t)(row * QROWB + ch * 16), Qh + g);
            CP_ASYNC16(sQl + (uint32_t)(row * QROWB + ch * 16), Ql + g);
        }
        CP_ASYNC_COMMIT();

        auto load_kv = [&](int bufi, int t) {
            const int key0 = t * 64;
            const uint32_t s0 = sSt + bufi * ATT_STAGE;
#pragma unroll
            for (int it = 0; it < 4; it++) {
                int idx = tid + it * 256;
                int row = idx >> 4, ch = idx & 15;
                CP_ASYNC16(s0 + (uint32_t)(row * KROWB + ch * 16),
                           Kh + (size_t)(key0 + row) * HIDN + hofs + ch * 8);
            }
#pragma unroll
            for (int it = 0; it < 4; it++) {
                int idx = tid + it * 256;
                int row = idx >> 4, ch = idx & 15;
                CP_ASYNC16(s0 + KTILE + (uint32_t)(row * KROWB + ch * 16),
                           Kl + (size_t)(key0 + row) * HIDN + hofs + ch * 8);
            }
#pragma unroll
            for (int it = 0; it < 4; it++) {
                int idx = tid + it * 256;
                int row = idx >> 3, ch = idx & 7;
                CP_ASYNC16(s0 + 2 * KTILE + (uint32_t)(row * VROWB + ch * 16),
                           Vt + (size_t)(hofs + row) * nk + key0 + ch * 8);
            }
            CP_ASYNC_COMMIT();
        };

        load_kv(0, 0);
        if (ntiles > 1) load_kv(1, 1);

        float mrow[2] = {-1e30f, -1e30f};
        float lrow[2] = {0.0f, 0.0f};
        float o[16][4];
#pragma unroll
        for (int g = 0; g < 16; g++)
#pragma unroll
            for (int r = 0; r < 4; r++) o[g][r] = 0.0f;

#pragma unroll 1
        for (int t = 0; t < ntiles; t++) {
            const int bufi = t & 1;
            if (t + 1 < ntiles) { CP_ASYNC_WAIT(1); } else { CP_ASYNC_WAIT(0); }
            __syncthreads();
            const uint32_t sK  = sSt + bufi * ATT_STAGE;
            const uint32_t sKl = sK + KTILE;
            const uint32_t sV  = sK + 2 * KTILE;

            // ---- S = Q K^T (3-term split bf16) ----
            float s[8][4];
#pragma unroll
            for (int nt = 0; nt < 8; nt++)
#pragma unroll
                for (int r = 0; r < 4; r++) s[nt][r] = 0.0f;

#pragma unroll
            for (int kk = 0; kk < 8; kk++) {
                uint32_t ah[4], al[4];
                ldsm_x4(ah, sQh + lrowq + kk * 32);
                ldsm_x4(al, sQl + lrowq + kk * 32);
#pragma unroll
                for (int g = 0; g < 4; g++) {
                    uint32_t bh[4], bl[4];
                    ldsm_x4(bh, sK  + g * (16 * KROWB) + lrowk + kk * 32);
                    ldsm_x4(bl, sKl + g * (16 * KROWB) + lrowk + kk * 32);
                    mma_bf16(s[2 * g],     ah, bh[0], bh[2]);
                    mma_bf16(s[2 * g + 1], ah, bh[1], bh[3]);
                    mma_bf16(s[2 * g],     ah, bl[0], bl[2]);
                    mma_bf16(s[2 * g + 1], ah, bl[1], bl[3]);
                    mma_bf16(s[2 * g],     al, bh[0], bh[2]);
                    mma_bf16(s[2 * g + 1], al, bh[1], bh[3]);
                }
            }

            // ---- online softmax (2 rows per thread) ----
#pragma unroll
            for (int i = 0; i < 2; i++) {
                float mx = mrow[i];
#pragma unroll
                for (int nt = 0; nt < 8; nt++)
                    mx = fmaxf(mx, fmaxf(s[nt][2 * i], s[nt][2 * i + 1]));
                mx = fmaxf(mx, __shfl_xor_sync(0xffffffffu, mx, 1));
                mx = fmaxf(mx, __shfl_xor_sync(0xffffffffu, mx, 2));
                const float alpha = __expf(mrow[i] - mx);
                mrow[i] = mx;
                float rs = 0.0f;
#pragma unroll
                for (int nt = 0; nt < 8; nt++) {
                    float p0 = __expf(s[nt][2 * i] - mx);
                    float p1 = __expf(s[nt][2 * i + 1] - mx);
                    s[nt][2 * i] = p0; s[nt][2 * i + 1] = p1;
                    rs += p0 + p1;
                }
                rs += __shfl_xor_sync(0xffffffffu, rs, 1);
                rs += __shfl_xor_sync(0xffffffffu, rs, 2);
                lrow[i] = lrow[i] * alpha + rs;
#pragma unroll
                for (int nt = 0; nt < 16; nt++) {
                    o[nt][2 * i] *= alpha; o[nt][2 * i + 1] *= alpha;
                }
            }

            // ---- P -> fp16 A-frags (in-register) ----
            uint32_t pa[4][4];
#pragma unroll
            for (int j = 0; j < 4; j++) {
                pa[j][0] = packf16(s[2 * j][0],     s[2 * j][1]);
                pa[j][1] = packf16(s[2 * j][2],     s[2 * j][3]);
                pa[j][2] = packf16(s[2 * j + 1][0], s[2 * j + 1][1]);
                pa[j][3] = packf16(s[2 * j + 1][2], s[2 * j + 1][3]);
            }

            // ---- O += P V (fp16) ----
#pragma unroll
            for (int j = 0; j < 4; j++) {
#pragma unroll
                for (int g = 0; g < 8; g++) {
                    uint32_t vb[4];
                    ldsm_x4(vb, sV + g * (16 * VROWB) + lrowv + j * 32);
                    mma_f16(o[2 * g],     pa[j], vb[0], vb[2]);
                    mma_f16(o[2 * g + 1], pa[j], vb[1], vb[3]);
                }
            }
            __syncthreads();
            if (t + 2 < ntiles) load_kv(bufi, t + 2);
        }

        // ---- epilogue ----
        const float inv0 = 1.0f / lrow[0];
        const float inv1 = 1.0f / lrow[1];
        const int r0 = q0 + w * 16 + (lane >> 2);
        const int cb = hofs + (lane & 3) * 2;
#pragma unroll
        for (int g = 0; g < 16; g++) {
            float* p0 = out + (size_t)r0 * HIDN + cb + g * 8;
            float* p1 = out + (size_t)(r0 + 8) * HIDN + cb + g * 8;
            if (pass == 0) {
                p0[0] = o[g][0] * inv0; p0[1] = o[g][1] * inv0;
                p1[0] = o[g][2] * inv1; p1[1] = o[g][3] * inv1;
            } else {
                p0[0] += o[g][0] * inv0; p0[1] += o[g][1] * inv0;
                p1[0] += o[g][2] * inv1; p1[1] += o[g][3] * inv1;
            }
        }
    }
}

// ---------------------------------------------------------------------------
// Launch
// ---------------------------------------------------------------------------
extern "C" void kernel_launch(void* const* d_in, const int* in_sizes, int n_in,
                              void* d_out, int out_size)
{
    const float* hidden = (const float*)d_in[0];
    const float* iph    = (const float*)d_in[1];
    const float* sinp   = (const float*)d_in[2];
    const float* cosp   = (const float*)d_in[3];
    const float* Wq     = (const float*)d_in[4];
    const float* bq     = (const float*)d_in[5];
    const float* Wk     = (const float*)d_in[6];
    const float* bk     = (const float*)d_in[7];
    const float* Wv     = (const float*)d_in[8];
    const float* bv     = (const float*)d_in[9];
    const float* Wo     = (const float*)d_in[10];
    const float* bo     = (const float*)d_in[11];
    const float* Wk_ip  = (const float*)d_in[12];
    const float* bk_ip  = (const float*)d_in[13];
    const float* Wv_ip  = (const float*)d_in[14];
    const float* bv_ip  = (const float*)d_in[15];
    const float* qscale = (const float*)d_in[16];
    const float* kscale = (const float*)d_in[17];

    float *q, *k, *v, *kip, *vip, *ao;
    cudaGetSymbolAddress((void**)&q,    g_q);
    cudaGetSymbolAddress((void**)&k,    g_k);
    cudaGetSymbolAddress((void**)&v,    g_v);
    cudaGetSymbolAddress((void**)&kip,  g_kip);
    cudaGetSymbolAddress((void**)&vip,  g_vip);
    cudaGetSymbolAddress((void**)&ao,   g_ao);

    __nv_bfloat16 *hb_hi, *hb_lo, *wq_hi, *wq_lo, *wk_hi, *wk_lo, *wv_hi, *wv_lo,
                  *wo_hi, *wo_lo, *wkip_hi, *wkip_lo, *wvip_hi, *wvip_lo,
                  *ip_hi, *ip_lo, *ao_hi, *ao_lo;
    __nv_bfloat16 *qr_hi, *qr_lo, *qn_hi, *qn_lo, *kr_hi, *kr_lo, *kipn_hi, *kipn_lo;
    __half *vt, *vipt;
    cudaGetSymbolAddress((void**)&hb_hi,   g_hb_hi);
    cudaGetSymbolAddress((void**)&hb_lo,   g_hb_lo);
    cudaGetSymbolAddress((void**)&wq_hi,   g_wq_hi);
    cudaGetSymbolAddress((void**)&wq_lo,   g_wq_lo);
    cudaGetSymbolAddress((void**)&wk_hi,   g_wk_hi);
    cudaGetSymbolAddress((void**)&wk_lo,   g_wk_lo);
    cudaGetSymbolAddress((void**)&wv_hi,   g_wv_hi);
    cudaGetSymbolAddress((void**)&wv_lo,   g_wv_lo);
    cudaGetSymbolAddress((void**)&wo_hi,   g_wo_hi);
    cudaGetSymbolAddress((void**)&wo_lo,   g_wo_lo);
    cudaGetSymbolAddress((void**)&wkip_hi, g_wkip_hi);
    cudaGetSymbolAddress((void**)&wkip_lo, g_wkip_lo);
    cudaGetSymbolAddress((void**)&wvip_hi, g_wvip_hi);
    cudaGetSymbolAddress((void**)&wvip_lo, g_wvip_lo);
    cudaGetSymbolAddress((void**)&ip_hi,   g_ip_hi);
    cudaGetSymbolAddress((void**)&ip_lo,   g_ip_lo);
    cudaGetSymbolAddress((void**)&ao_hi,   g_ao_hi);
    cudaGetSymbolAddress((void**)&ao_lo,   g_ao_lo);
    cudaGetSymbolAddress((void**)&qr_hi,   g_qr_hi);
    cudaGetSymbolAddress((void**)&qr_lo,   g_qr_lo);
    cudaGetSymbolAddress((void**)&qn_hi,   g_qn_hi);
    cudaGetSymbolAddress((void**)&qn_lo,   g_qn_lo);
    cudaGetSymbolAddress((void**)&kr_hi,   g_kr_hi);
    cudaGetSymbolAddress((void**)&kr_lo,   g_kr_lo);
    cudaGetSymbolAddress((void**)&kipn_hi, g_kipn_hi);
    cudaGetSymbolAddress((void**)&kipn_lo, g_kipn_lo);
    cudaGetSymbolAddress((void**)&vt,      g_vt);
    cudaGetSymbolAddress((void**)&vipt,    g_vipt);

    auto cvt = [&](const float* src, __nv_bfloat16* hi, __nv_bfloat16* lo, int n) {
        int n4 = n / 4;
        cvt_split<<<(n4 + 255) / 256, 256>>>(src, hi, lo, n4);
    };
    cvt(hidden, hb_hi, hb_lo, S_LEN * HIDN);
    cvt(Wq, wq_hi, wq_lo, HIDN * HIDN);
    cvt(Wk, wk_hi, wk_lo, HIDN * HIDN);
    cvt(Wv, wv_hi, wv_lo, HIDN * HIDN);
    cvt(Wo, wo_hi, wo_lo, HIDN * HIDN);
    cvt(Wk_ip, wkip_hi, wkip_lo, HIDN * IPDIM);
    cvt(Wv_ip, wvip_hi, wvip_lo, HIDN * IPDIM);
    cvt(iph, ip_hi, ip_lo, IPSEQ * IPDIM);

    cudaFuncSetAttribute(gemm_mma, cudaFuncAttributeMaxDynamicSharedMemorySize, GEMM_DSMEM);
    cudaFuncSetAttribute(attn_mma, cudaFuncAttributeMaxDynamicSharedMemorySize, ATT_SMEM);

    const dim3 g_big(HIDN / 128, S_LEN / 128);   // (24, 16)
    const dim3 g_ip (HIDN / 128, IPSEQ / 128);   // (24, 4)

    gemm_mma<<<g_big, 256, GEMM_DSMEM>>>(hb_hi, hb_lo, wq_hi, wq_lo, bq, q, S_LEN, HIDN, HIDN);
    gemm_mma<<<g_big, 256, GEMM_DSMEM>>>(hb_hi, hb_lo, wk_hi, wk_lo, bk, k, S_LEN, HIDN, HIDN);
    gemm_mma<<<g_big, 256, GEMM_DSMEM>>>(hb_hi, hb_lo, wv_hi, wv_lo, bv, v, S_LEN, HIDN, HIDN);
    gemm_mma<<<g_ip,  256, GEMM_DSMEM>>>(ip_hi, ip_lo, wkip_hi, wkip_lo, bk_ip, kip, IPSEQ, HIDN, IPDIM);
    gemm_mma<<<g_ip,  256, GEMM_DSMEM>>>(ip_hi, ip_lo, wvip_hi, wvip_lo, bv_ip, vip, IPSEQ, HIDN, IPDIM);

    prep_q_kernel  <<<dim3(S_LEN, NH), 128>>>(q, sinp, cosp, qscale, qr_hi, qr_lo, qn_hi, qn_lo);
    prep_k_kernel  <<<dim3(S_LEN, NH), 128>>>(k, sinp, cosp, kr_hi, kr_lo);
    prep_kip_kernel<<<dim3(IPSEQ, NH), 128>>>(kip, kscale, kipn_hi, kipn_lo);
    transpose_half <<<dim3(S_LEN / 32, HD / 32, NH), 256>>>(v, vt, S_LEN);
    transpose_half <<<dim3(IPSEQ / 32, HD / 32, NH), 256>>>(vip, vipt, IPSEQ);

    attn_mma<<<dim3(S_LEN / 128, NH), 256, ATT_SMEM>>>(
        qr_hi, qr_lo, qn_hi, qn_lo, kr_hi, kr_lo, kipn_hi, kipn_lo, vt, vipt, ao);

    cvt(ao, ao_hi, ao_lo, S_LEN * HIDN);
    gemm_mma<<<g_big, 256, GEMM_DSMEM>>>(ao_hi, ao_lo, wo_hi, wo_lo, bo, (float*)d_out, S_LEN, HIDN, HIDN);
}

// round 6
// speedup vs baseline: 3.1534x; 1.0604x over previous
#include <cuda_runtime.h>
#include <cuda_bf16.h>
#include <cuda_fp16.h>
#include <cstdint>
#include <cstddef>

// ---------------------------------------------------------------------------
// Problem constants (FluxIPAttnProcessor: B=1, S=2048, H=24, D=128)
// ---------------------------------------------------------------------------
#define S_LEN 2048
#define HIDN  3072
#define NH    24
#define HD    128
#define IPSEQ 512
#define IPDIM 1152

#define DEV_INLINE __device__ __forceinline__

// ---------------------------------------------------------------------------
// PTX helpers: cp.async + ldmatrix + mma.sync (baseline sm_80+ PTX only)
// ---------------------------------------------------------------------------
#define CP_ASYNC16(smaddr, gptr) \
    asm volatile("cp.async.cg.shared.global [%0], [%1], 16;" :: "r"(smaddr), "l"(gptr) : "memory")
#define CP_ASYNC_COMMIT() asm volatile("cp.async.commit_group;" ::: "memory")
#define CP_ASYNC_WAIT(n)  asm volatile("cp.async.wait_group %0;" :: "n"(n) : "memory")

DEV_INLINE void ldsm_x4(uint32_t* r, uint32_t addr) {
    asm volatile("ldmatrix.sync.aligned.m8n8.x4.shared.b16 {%0,%1,%2,%3}, [%4];"
        : "=r"(r[0]), "=r"(r[1]), "=r"(r[2]), "=r"(r[3]) : "r"(addr));
}

DEV_INLINE void mma_bf16(float* d, const uint32_t* a, uint32_t b0, uint32_t b1) {
    asm volatile(
        "mma.sync.aligned.m16n8k16.row.col.f32.bf16.bf16.f32 "
        "{%0,%1,%2,%3}, {%4,%5,%6,%7}, {%8,%9}, {%0,%1,%2,%3};"
        : "+f"(d[0]), "+f"(d[1]), "+f"(d[2]), "+f"(d[3])
        : "r"(a[0]), "r"(a[1]), "r"(a[2]), "r"(a[3]), "r"(b0), "r"(b1));
}

DEV_INLINE void mma_f16(float* d, const uint32_t* a, uint32_t b0, uint32_t b1) {
    asm volatile(
        "mma.sync.aligned.m16n8k16.row.col.f32.f16.f16.f32 "
        "{%0,%1,%2,%3}, {%4,%5,%6,%7}, {%8,%9}, {%0,%1,%2,%3};"
        : "+f"(d[0]), "+f"(d[1]), "+f"(d[2]), "+f"(d[3])
        : "r"(a[0]), "r"(a[1]), "r"(a[2]), "r"(a[3]), "r"(b0), "r"(b1));
}

// pack two f32 -> f16x2 register (lo lane = first arg)
DEV_INLINE uint32_t packf16(float lo, float hi) {
    uint32_t r;
    asm("cvt.rn.f16x2.f32 %0, %1, %2;" : "=r"(r) : "f"(hi), "f"(lo));
    return r;
}

// ---------------------------------------------------------------------------
// Device scratch
// ---------------------------------------------------------------------------
__device__ float g_q   [S_LEN * HIDN];
__device__ float g_k   [S_LEN * HIDN];
__device__ float g_v   [S_LEN * HIDN];
__device__ float g_kip [IPSEQ * HIDN];
__device__ float g_vip [IPSEQ * HIDN];
__device__ float g_ao  [S_LEN * HIDN];

__device__ __nv_bfloat16 g_hb_hi [S_LEN * HIDN];
__device__ __nv_bfloat16 g_hb_lo [S_LEN * HIDN];
__device__ __nv_bfloat16 g_wq_hi [HIDN * HIDN];
__device__ __nv_bfloat16 g_wq_lo [HIDN * HIDN];
__device__ __nv_bfloat16 g_wk_hi [HIDN * HIDN];
__device__ __nv_bfloat16 g_wk_lo [HIDN * HIDN];
__device__ __nv_bfloat16 g_wv_hi [HIDN * HIDN];
__device__ __nv_bfloat16 g_wv_lo [HIDN * HIDN];
__device__ __nv_bfloat16 g_wo_hi [HIDN * HIDN];
__device__ __nv_bfloat16 g_wo_lo [HIDN * HIDN];
__device__ __nv_bfloat16 g_wkip_hi[HIDN * IPDIM];
__device__ __nv_bfloat16 g_wkip_lo[HIDN * IPDIM];
__device__ __nv_bfloat16 g_wvip_hi[HIDN * IPDIM];
__device__ __nv_bfloat16 g_wvip_lo[HIDN * IPDIM];
__device__ __nv_bfloat16 g_ip_hi [IPSEQ * IPDIM];
__device__ __nv_bfloat16 g_ip_lo [IPSEQ * IPDIM];
__device__ __nv_bfloat16 g_ao_hi [S_LEN * HIDN];
__device__ __nv_bfloat16 g_ao_lo [S_LEN * HIDN];

// attention operands (bf16 hi/lo) + fp16 transposed V
__device__ __nv_bfloat16 g_qr_hi [S_LEN * HIDN];
__device__ __nv_bfloat16 g_qr_lo [S_LEN * HIDN];
__device__ __nv_bfloat16 g_qn_hi [S_LEN * HIDN];
__device__ __nv_bfloat16 g_qn_lo [S_LEN * HIDN];
__device__ __nv_bfloat16 g_kr_hi [S_LEN * HIDN];
__device__ __nv_bfloat16 g_kr_lo [S_LEN * HIDN];
__device__ __nv_bfloat16 g_kipn_hi[IPSEQ * HIDN];
__device__ __nv_bfloat16 g_kipn_lo[IPSEQ * HIDN];
__device__ __half g_vt  [NH * HD * S_LEN];
__device__ __half g_vipt[NH * HD * IPSEQ];

// ---------------------------------------------------------------------------
// Batched fp32 -> (bf16 hi, bf16 lo) split conversion (up to 4 tensors/launch)
// ---------------------------------------------------------------------------
struct CSet {
    const float* x;
    __nv_bfloat16* hi;
    __nv_bfloat16* lo;
    int n4;
};

__global__ void cvt_multi(CSet a, CSet b, CSet c, CSet d)
{
    CSet s = (blockIdx.y == 0) ? a : (blockIdx.y == 1) ? b
           : (blockIdx.y == 2) ? c : d;
    int i = blockIdx.x * blockDim.x + threadIdx.x;
    if (i >= s.n4) return;
    float4 v = ((const float4*)s.x)[i];
    __nv_bfloat16 h0 = __float2bfloat16(v.x);
    __nv_bfloat16 h1 = __float2bfloat16(v.y);
    __nv_bfloat16 h2 = __float2bfloat16(v.z);
    __nv_bfloat16 h3 = __float2bfloat16(v.w);
    __nv_bfloat16 l0 = __float2bfloat16(v.x - __bfloat162float(h0));
    __nv_bfloat16 l1 = __float2bfloat16(v.y - __bfloat162float(h1));
    __nv_bfloat16 l2 = __float2bfloat16(v.z - __bfloat162float(h2));
    __nv_bfloat16 l3 = __float2bfloat16(v.w - __bfloat162float(h3));
    __nv_bfloat162 hp0; hp0.x = h0; hp0.y = h1;
    __nv_bfloat162 hp1; hp1.x = h2; hp1.y = h3;
    __nv_bfloat162 lp0; lp0.x = l0; lp0.y = l1;
    __nv_bfloat162 lp1; lp1.x = l2; lp1.y = l3;
    ((__nv_bfloat162*)s.hi)[2 * i]     = hp0;
    ((__nv_bfloat162*)s.hi)[2 * i + 1] = hp1;
    ((__nv_bfloat162*)s.lo)[2 * i]     = lp0;
    ((__nv_bfloat162*)s.lo)[2 * i + 1] = lp1;
}

// ---------------------------------------------------------------------------
// transpose V: fp32 [s][h*HD+d] -> fp16 vt[(h*HD+d)*seqlen + s]
// ---------------------------------------------------------------------------
__global__ void transpose_half(const float* __restrict__ v, __half* __restrict__ vt,
                               int seqlen)
{
    __shared__ float t[32][33];
    const int s0 = blockIdx.x * 32, d0 = blockIdx.y * 32, h = blockIdx.z;
    const int tx = threadIdx.x & 31, ty = threadIdx.x >> 5;
#pragma unroll
    for (int i = 0; i < 4; i++) {
        int row = ty + i * 8;
        t[row][tx] = v[(size_t)(s0 + row) * HIDN + h * HD + d0 + tx];
    }
    __syncthreads();
#pragma unroll
    for (int i = 0; i < 4; i++) {
        int d = ty + i * 8;
        vt[(size_t)(h * HD + d0 + d) * seqlen + s0 + tx] = __float2half(t[tx][d]);
    }
}

// ---------------------------------------------------------------------------
// mma.sync split-bf16 GEMM, fused multi-output (up to 3 weight sets).
// For blockIdx.x in [sel*nper, (sel+1)*nper): C_sel[M,3072] = A*B_sel^T + bias.
// 3-stage cp.async pipeline; CTA tile 128x128; 3-term hi/lo accumulation.
// ---------------------------------------------------------------------------
#define KC 64
#define ROWB 144
#define TILEB (128 * ROWB)             // 18432
#define STAGEB (4 * TILEB)             // 73728
#define GEMM_DSMEM (3 * STAGEB)        // 221184

struct GSet {
    const __nv_bfloat16* bhi;
    const __nv_bfloat16* blo;
    const float* bias;
    float* C;
};

__global__ void __launch_bounds__(256, 1) gemm_mma_f(
    const __nv_bfloat16* __restrict__ Ahi, const __nv_bfloat16* __restrict__ Alo,
    GSet s0, GSet s1, GSet s2, int nper, int N, int K)
{
    extern __shared__ __align__(128) char smem[];
    const uint32_t sbase = (uint32_t)__cvta_generic_to_shared(smem);
    const int tid  = threadIdx.x;
    const int lane = tid & 31;
    const int w    = tid >> 5;
    const int wm   = w >> 1;
    const int wn   = w & 1;

    const int sel = blockIdx.x / nper;
    const GSet S = (sel == 0) ? s0 : (sel == 1) ? s1 : s2;
    const __nv_bfloat16* __restrict__ Bhi = S.bhi;
    const __nv_bfloat16* __restrict__ Blo = S.blo;

    const int m0 = blockIdx.y * 128;
    const int n0 = (blockIdx.x % nper) * 128;

    auto load_stage = [&](int buf, int kt) {
        const int k0 = kt * KC;
        const uint32_t sb = sbase + buf * STAGEB;
#pragma unroll
        for (int op = 0; op < 4; op++) {
            const __nv_bfloat16* src = (op == 0) ? Ahi : (op == 1) ? Alo
                                      : (op == 2) ? Bhi : Blo;
            const int r0 = (op < 2) ? m0 : n0;
            const uint32_t so = sb + op * TILEB;
#pragma unroll
            for (int it = 0; it < 4; it++) {
                int idx = tid + it * 256;
                int row = idx >> 3;
                int ch  = idx & 7;
                uint32_t sa = so + (uint32_t)(row * ROWB + ch * 16);
                const void* g = (const void*)(src + (size_t)(r0 + row) * K + k0 + ch * 8);
                CP_ASYNC16(sa, g);
            }
        }
        CP_ASYNC_COMMIT();
    };

    float c[2][8][4];
#pragma unroll
    for (int mt = 0; mt < 2; mt++)
#pragma unroll
        for (int nt = 0; nt < 8; nt++)
#pragma unroll
            for (int r = 0; r < 4; r++) c[mt][nt][r] = 0.0f;

    const int T = K / KC;
    load_stage(0, 0);
    if (T > 1) load_stage(1, 1);

    int buf = 0;
#pragma unroll 1
    for (int i = 0; i < T; i++) {
        if (i + 1 < T) { CP_ASYNC_WAIT(1); } else { CP_ASYNC_WAIT(0); }
        __syncthreads();
        if (i + 2 < T) {
            int nb = buf + 2; if (nb >= 3) nb -= 3;
            load_stage(nb, i + 2);
        }

        const uint32_t sb   = sbase + buf * STAGEB;
        const uint32_t sAhi = sb;
        const uint32_t sAlo = sb + TILEB;
        const uint32_t sBhi = sb + 2 * TILEB;
        const uint32_t sBlo = sb + 3 * TILEB;

#pragma unroll
        for (int ks = 0; ks < 4; ks++) {
            uint32_t ah[2][4], al[2][4], bh[4][4], bl[4][4];
#pragma unroll
            for (int mt = 0; mt < 2; mt++) {
                int row = wm * 32 + mt * 16 + (lane & 15);
                uint32_t off = (uint32_t)(row * ROWB + (lane >> 4) * 16 + ks * 32);
                ldsm_x4(ah[mt], sAhi + off);
                ldsm_x4(al[mt], sAlo + off);
            }
#pragma unroll
            for (int bq = 0; bq < 4; bq++) {
                int nrow = wn * 64 + bq * 16 + ((lane >> 4) << 3) + (lane & 7);
                uint32_t off = (uint32_t)(nrow * ROWB + ((lane >> 3) & 1) * 16 + ks * 32);
                ldsm_x4(bh[bq], sBhi + off);
                ldsm_x4(bl[bq], sBlo + off);
            }
#pragma unroll
            for (int mt = 0; mt < 2; mt++) {
#pragma unroll
                for (int bq = 0; bq < 4; bq++) {
                    mma_bf16(c[mt][2 * bq],     ah[mt], bh[bq][0], bh[bq][1]);
                    mma_bf16(c[mt][2 * bq + 1], ah[mt], bh[bq][2], bh[bq][3]);
                    mma_bf16(c[mt][2 * bq],     ah[mt], bl[bq][0], bl[bq][1]);
                    mma_bf16(c[mt][2 * bq + 1], ah[mt], bl[bq][2], bl[bq][3]);
                    mma_bf16(c[mt][2 * bq],     al[mt], bh[bq][0], bh[bq][1]);
                    mma_bf16(c[mt][2 * bq + 1], al[mt], bh[bq][2], bh[bq][3]);
                }
            }
        }
        __syncthreads();
        buf = (buf + 1 == 3) ? 0 : buf + 1;
    }

    const int crow  = wm * 32 + (lane >> 2);
    const int ccol0 = wn * 64 + (lane & 3) * 2;
#pragma unroll
    for (int mt = 0; mt < 2; mt++) {
#pragma unroll
        for (int nt = 0; nt < 8; nt++) {
            const int r  = m0 + crow + mt * 16;
            const int cc = n0 + ccol0 + nt * 8;
            const float b0v = S.bias[cc], b1v = S.bias[cc + 1];
            float* p  = S.C + (size_t)r * N + cc;
            float* p2 = p + 8 * N;
            p[0]  = c[mt][nt][0] + b0v;
            p[1]  = c[mt][nt][1] + b1v;
            p2[0] = c[mt][nt][2] + b0v;
            p2[1] = c[mt][nt][3] + b1v;
        }
    }
}

// ---------------------------------------------------------------------------
// Prep kernels: RoPE + RMSNorm, writing split bf16 outputs
// ---------------------------------------------------------------------------
DEV_INLINE float blk_sumsq(float x, float* red, int d) {
    float v = x * x;
#pragma unroll
    for (int o = 16; o > 0; o >>= 1) v += __shfl_xor_sync(0xffffffffu, v, o);
    if ((d & 31) == 0) red[d >> 5] = v;
    __syncthreads();
    return red[0] + red[1] + red[2] + red[3];
}

DEV_INLINE void split_store(__nv_bfloat16* hi, __nv_bfloat16* lo, size_t idx, float x) {
    __nv_bfloat16 h = __float2bfloat16(x);
    hi[idx] = h;
    lo[idx] = __float2bfloat16(x - __bfloat162float(h));
}

__global__ void prep_q_kernel(const float* __restrict__ q,
                              const float* __restrict__ sinp, const float* __restrict__ cosp,
                              const float* __restrict__ qscale,
                              __nv_bfloat16* __restrict__ qr_hi, __nv_bfloat16* __restrict__ qr_lo,
                              __nv_bfloat16* __restrict__ qn_hi, __nv_bfloat16* __restrict__ qn_lo)
{
    __shared__ float red[4];
    const int s = blockIdx.x, hh = blockIdx.y, d = threadIdx.x;
    const size_t base = (size_t)s * HIDN + hh * HD;
    const float x = q[base + d];
    const float ss = blk_sumsq(x, red, d);
    const float rms = sqrtf(ss * (1.0f / 128.0f));
    const float inv = 1.0f / (rms + 1e-6f);
    split_store(qn_hi, qn_lo, base + d, qscale[d] * x * inv * 0.08838834764831845f);
    float outv;
    if (d < 64) {
        float rot = (d < 32) ? -q[base + d + 32] : q[base + d - 32];
        outv = x * cosp[s * 64 + d] + rot * sinp[s * 64 + d];
    } else {
        outv = x;
    }
    split_store(qr_hi, qr_lo, base + d, outv);
}

__global__ void prep_k_kernel(const float* __restrict__ k,
                              const float* __restrict__ sinp, const float* __restrict__ cosp,
                              __nv_bfloat16* __restrict__ kr_hi, __nv_bfloat16* __restrict__ kr_lo)
{
    const int s = blockIdx.x, hh = blockIdx.y, d = threadIdx.x;
    const size_t base = (size_t)s * HIDN + hh * HD;
    const float x = k[base + d];
    float outv;
    if (d < 64) {
        float rot = (d < 32) ? -k[base + d + 32] : k[base + d - 32];
        outv = x * cosp[s * 64 + d] + rot * sinp[s * 64 + d];
    } else {
        outv = x;
    }
    split_store(kr_hi, kr_lo, base + d, outv);
}

__global__ void prep_kip_kernel(const float* __restrict__ kip,
                                const float* __restrict__ kscale,
                                __nv_bfloat16* __restrict__ kn_hi, __nv_bfloat16* __restrict__ kn_lo)
{
    __shared__ float red[4];
    const int s = blockIdx.x, hh = blockIdx.y, d = threadIdx.x;
    const size_t base = (size_t)s * HIDN + hh * HD;
    const float x = kip[base + d];
    const float ss = blk_sumsq(x, red, d);
    const float rms = sqrtf(ss * (1.0f / 128.0f));
    const float inv = 1.0f / (rms + 1e-6f);
    split_store(kn_hi, kn_lo, base + d, kscale[d] * x * inv * 0.08838834764831845f);
}

// ---------------------------------------------------------------------------
// mma.sync fused two-context flash attention.
// Grid (S/128, NH), 256 threads (8 warps). Warp = 16 q-rows x 64 keys.
// Q fragments register-resident per pass (loaded once, reused for all tiles).
// S = QK^T: split-bf16 3-term; softmax fp32; P*V: fp16 single-term.
// ---------------------------------------------------------------------------
#define QROWB 272
#define KROWB 272
#define VROWB 144
#define QTILE (128 * QROWB)            // 34816
#define KTILE (64 * KROWB)             // 17408
#define VTILE (128 * VROWB)            // 18432
#define ATT_STAGE (2 * KTILE + VTILE)  // 53248
#define ATT_SMEM (2 * QTILE + 2 * ATT_STAGE)  // 176128

__global__ void __launch_bounds__(256, 1) attn_mma(
    const __nv_bfloat16* __restrict__ qr_hi, const __nv_bfloat16* __restrict__ qr_lo,
    const __nv_bfloat16* __restrict__ qn_hi, const __nv_bfloat16* __restrict__ qn_lo,
    const __nv_bfloat16* __restrict__ kr_hi, const __nv_bfloat16* __restrict__ kr_lo,
    const __nv_bfloat16* __restrict__ kip_hi, const __nv_bfloat16* __restrict__ kip_lo,
    const __half* __restrict__ vtp, const __half* __restrict__ viptp,
    float* __restrict__ out)
{
    extern __shared__ __align__(128) char smem[];
    const uint32_t sb  = (uint32_t)__cvta_generic_to_shared(smem);
    const uint32_t sQh = sb, sQl = sb + QTILE;
    const uint32_t sSt = sb + 2 * QTILE;

    const int h = blockIdx.y, q0 = blockIdx.x * 128, hofs = h * HD;
    const int tid = threadIdx.x, lane = tid & 31, w = tid >> 5;

    const uint32_t lrowq = (uint32_t)((w * 16 + (lane & 15)) * QROWB + (lane >> 4) * 16);
    const uint32_t lrowk = (uint32_t)((lane & 15) * KROWB + (lane >> 4) * 16);
    const uint32_t lrowv = (uint32_t)((lane & 15) * VROWB + (lane >> 4) * 16);

#pragma unroll 1
    for (int pass = 0; pass < 2; pass++) {
        const __nv_bfloat16* Qh = pass ? qn_hi  : qr_hi;
        const __nv_bfloat16* Ql = pass ? qn_lo  : qr_lo;
        const __nv_bfloat16* Kh = pass ? kip_hi : kr_hi;
        const __nv_bfloat16* Kl = pass ? kip_lo : kr_lo;
        const __half* Vt = pass ? viptp : vtp;
        const int nk = pass ? IPSEQ : S_LEN;
        const int ntiles = nk >> 6;

        __syncthreads();   // protect Q smem + stage-0 K/V across passes
        // Q hi+lo: 128 rows x 16 chunks each
#pragma unroll
        for (int it = 0; it < 8; it++) {
            int idx = tid + it * 256;
            int row = idx >> 4, ch = idx & 15;
            const size_t g = (size_t)(q0 + row) * HIDN + hofs + ch * 8;
            CP_ASYNC16(sQh + (uint32_t)(row * QROWB + ch * 16), Qh + g);
            CP_ASYNC16(sQl + (uint32_t)(row * QROWB + ch * 16), Ql + g);
        }
        CP_ASYNC_COMMIT();

        auto load_kv = [&](int bufi, int t) {
            const int key0 = t * 64;
            const uint32_t s0 = sSt + bufi * ATT_STAGE;
#pragma unroll
            for (int it = 0; it < 4; it++) {
                int idx = tid + it * 256;
                int row = idx >> 4, ch = idx & 15;
                CP_ASYNC16(s0 + (uint32_t)(row * KROWB + ch * 16),
                           Kh + (size_t)(key0 + row) * HIDN + hofs + ch * 8);
            }
#pragma unroll
            for (int it = 0; it < 4; it++) {
                int idx = tid + it * 256;
                int row = idx >> 4, ch = idx & 15;
                CP_ASYNC16(s0 + KTILE + (uint32_t)(row * KROWB + ch * 16),
                           Kl + (size_t)(key0 + row) * HIDN + hofs + ch * 8);
            }
#pragma unroll
            for (int it = 0; it < 4; it++) {
                int idx = tid + it * 256;
                int row = idx >> 3, ch = idx & 7;
                CP_ASYNC16(s0 + 2 * KTILE + (uint32_t)(row * VROWB + ch * 16),
                           Vt + (size_t)(hofs + row) * nk + key0 + ch * 8);
            }
            CP_ASYNC_COMMIT();
        };

        load_kv(0, 0);
        if (ntiles > 1) load_kv(1, 1);

        // --- load Q fragments once (register-resident for all key tiles) ---
        uint32_t qh[8][4], ql[8][4];
        CP_ASYNC_WAIT(2);   // Q group complete (kv0/kv1 may be pending)
        __syncthreads();
#pragma unroll
        for (int kk = 0; kk < 8; kk++) {
            ldsm_x4(qh[kk], sQh + lrowq + kk * 32);
            ldsm_x4(ql[kk], sQl + lrowq + kk * 32);
        }

        float mrow[2] = {-1e30f, -1e30f};
        float lrow[2] = {0.0f, 0.0f};
        float o[16][4];
#pragma unroll
        for (int g = 0; g < 16; g++)
#pragma unroll
            for (int r = 0; r < 4; r++) o[g][r] = 0.0f;

#pragma unroll 1
        for (int t = 0; t < ntiles; t++) {
            const int bufi = t & 1;
            if (t + 1 < ntiles) { CP_ASYNC_WAIT(1); } else { CP_ASYNC_WAIT(0); }
            __syncthreads();
            const uint32_t sK  = sSt + bufi * ATT_STAGE;
            const uint32_t sKl = sK + KTILE;
            const uint32_t sV  = sK + 2 * KTILE;

            // ---- S = Q K^T (3-term split bf16, Q frags in regs) ----
            float s[8][4];
#pragma unroll
            for (int nt = 0; nt < 8; nt++)
#pragma unroll
                for (int r = 0; r < 4; r++) s[nt][r] = 0.0f;

#pragma unroll
            for (int kk = 0; kk < 8; kk++) {
#pragma unroll
                for (int g = 0; g < 4; g++) {
                    uint32_t bh[4], bl[4];
                    ldsm_x4(bh, sK  + g * (16 * KROWB) + lrowk + kk * 32);
                    ldsm_x4(bl, sKl + g * (16 * KROWB) + lrowk + kk * 32);
                    mma_bf16(s[2 * g],     qh[kk], bh[0], bh[2]);
                    mma_bf16(s[2 * g + 1], qh[kk], bh[1], bh[3]);
                    mma_bf16(s[2 * g],     qh[kk], bl[0], bl[2]);
                    mma_bf16(s[2 * g + 1], qh[kk], bl[1], bl[3]);
                    mma_bf16(s[2 * g],     ql[kk], bh[0], bh[2]);
                    mma_bf16(s[2 * g + 1], ql[kk], bh[1], bh[3]);
                }
            }

            // ---- online softmax (2 rows per thread) ----
#pragma unroll
            for (int i = 0; i < 2; i++) {
                float mx = mrow[i];
#pragma unroll
                for (int nt = 0; nt < 8; nt++)
                    mx = fmaxf(mx, fmaxf(s[nt][2 * i], s[nt][2 * i + 1]));
                mx = fmaxf(mx, __shfl_xor_sync(0xffffffffu, mx, 1));
                mx = fmaxf(mx, __shfl_xor_sync(0xffffffffu, mx, 2));
                const float alpha = __expf(mrow[i] - mx);
                mrow[i] = mx;
                float rs = 0.0f;
#pragma unroll
                for (int nt = 0; nt < 8; nt++) {
                    float p0 = __expf(s[nt][2 * i] - mx);
                    float p1 = __expf(s[nt][2 * i + 1] - mx);
                    s[nt][2 * i] = p0; s[nt][2 * i + 1] = p1;
                    rs += p0 + p1;
                }
                rs += __shfl_xor_sync(0xffffffffu, rs, 1);
                rs += __shfl_xor_sync(0xffffffffu, rs, 2);
                lrow[i] = lrow[i] * alpha + rs;
#pragma unroll
                for (int nt = 0; nt < 16; nt++) {
                    o[nt][2 * i] *= alpha; o[nt][2 * i + 1] *= alpha;
                }
            }

            // ---- P -> fp16 A-frags (in-register) ----
            uint32_t pa[4][4];
#pragma unroll
            for (int j = 0; j < 4; j++) {
                pa[j][0] = packf16(s[2 * j][0],     s[2 * j][1]);
                pa[j][1] = packf16(s[2 * j][2],     s[2 * j][3]);
                pa[j][2] = packf16(s[2 * j + 1][0], s[2 * j + 1][1]);
                pa[j][3] = packf16(s[2 * j + 1][2], s[2 * j + 1][3]);
            }

            // ---- O += P V (fp16) ----
#pragma unroll
            for (int j = 0; j < 4; j++) {
#pragma unroll
                for (int g = 0; g < 8; g++) {
                    uint32_t vb[4];
                    ldsm_x4(vb, sV + g * (16 * VROWB) + lrowv + j * 32);
                    mma_f16(o[2 * g],     pa[j], vb[0], vb[2]);
                    mma_f16(o[2 * g + 1], pa[j], vb[1], vb[3]);
                }
            }
            __syncthreads();
            if (t + 2 < ntiles) load_kv(bufi, t + 2);
        }

        // ---- epilogue ----
        const float inv0 = 1.0f / lrow[0];
        const float inv1 = 1.0f / lrow[1];
        const int r0 = q0 + w * 16 + (lane >> 2);
        const int cb = hofs + (lane & 3) * 2;
#pragma unroll
        for (int g = 0; g < 16; g++) {
            float* p0 = out + (size_t)r0 * HIDN + cb + g * 8;
            float* p1 = out + (size_t)(r0 + 8) * HIDN + cb + g * 8;
            if (pass == 0) {
                p0[0] = o[g][0] * inv0; p0[1] = o[g][1] * inv0;
                p1[0] = o[g][2] * inv1; p1[1] = o[g][3] * inv1;
            } else {
                p0[0] += o[g][0] * inv0; p0[1] += o[g][1] * inv0;
                p1[0] += o[g][2] * inv1; p1[1] += o[g][3] * inv1;
            }
        }
    }
}

// ---------------------------------------------------------------------------
// Launch
// ---------------------------------------------------------------------------
extern "C" void kernel_launch(void* const* d_in, const int* in_sizes, int n_in,
                              void* d_out, int out_size)
{
    const float* hidden = (const float*)d_in[0];
    const float* iph    = (const float*)d_in[1];
    const float* sinp   = (const float*)d_in[2];
    const float* cosp   = (const float*)d_in[3];
    const float* Wq     = (const float*)d_in[4];
    const float* bq     = (const float*)d_in[5];
    const float* Wk     = (const float*)d_in[6];
    const float* bk     = (const float*)d_in[7];
    const float* Wv     = (const float*)d_in[8];
    const float* bv     = (const float*)d_in[9];
    const float* Wo     = (const float*)d_in[10];
    const float* bo     = (const float*)d_in[11];
    const float* Wk_ip  = (const float*)d_in[12];
    const float* bk_ip  = (const float*)d_in[13];
    const float* Wv_ip  = (const float*)d_in[14];
    const float* bv_ip  = (const float*)d_in[15];
    const float* qscale = (const float*)d_in[16];
    const float* kscale = (const float*)d_in[17];

    float *q, *k, *v, *kip, *vip, *ao;
    cudaGetSymbolAddress((void**)&q,    g_q);
    cudaGetSymbolAddress((void**)&k,    g_k);
    cudaGetSymbolAddress((void**)&v,    g_v);
    cudaGetSymbolAddress((void**)&kip,  g_kip);
    cudaGetSymbolAddress((void**)&vip,  g_vip);
    cudaGetSymbolAddress((void**)&ao,   g_ao);

    __nv_bfloat16 *hb_hi, *hb_lo, *wq_hi, *wq_lo, *wk_hi, *wk_lo, *wv_hi, *wv_lo,
                  *wo_hi, *wo_lo, *wkip_hi, *wkip_lo, *wvip_hi, *wvip_lo,
                  *ip_hi, *ip_lo, *ao_hi, *ao_lo;
    __nv_bfloat16 *qr_hi, *qr_lo, *qn_hi, *qn_lo, *kr_hi, *kr_lo, *kipn_hi, *kipn_lo;
    __half *vt, *vipt;
    cudaGetSymbolAddress((void**)&hb_hi,   g_hb_hi);
    cudaGetSymbolAddress((void**)&hb_lo,   g_hb_lo);
    cudaGetSymbolAddress((void**)&wq_hi,   g_wq_hi);
    cudaGetSymbolAddress((void**)&wq_lo,   g_wq_lo);
    cudaGetSymbolAddress((void**)&wk_hi,   g_wk_hi);
    cudaGetSymbolAddress((void**)&wk_lo,   g_wk_lo);
    cudaGetSymbolAddress((void**)&wv_hi,   g_wv_hi);
    cudaGetSymbolAddress((void**)&wv_lo,   g_wv_lo);
    cudaGetSymbolAddress((void**)&wo_hi,   g_wo_hi);
    cudaGetSymbolAddress((void**)&wo_lo,   g_wo_lo);
    cudaGetSymbolAddress((void**)&wkip_hi, g_wkip_hi);
    cudaGetSymbolAddress((void**)&wkip_lo, g_wkip_lo);
    cudaGetSymbolAddress((void**)&wvip_hi, g_wvip_hi);
    cudaGetSymbolAddress((void**)&wvip_lo, g_wvip_lo);
    cudaGetSymbolAddress((void**)&ip_hi,   g_ip_hi);
    cudaGetSymbolAddress((void**)&ip_lo,   g_ip_lo);
    cudaGetSymbolAddress((void**)&ao_hi,   g_ao_hi);
    cudaGetSymbolAddress((void**)&ao_lo,   g_ao_lo);
    cudaGetSymbolAddress((void**)&qr_hi,   g_qr_hi);
    cudaGetSymbolAddress((void**)&qr_lo,   g_qr_lo);
    cudaGetSymbolAddress((void**)&qn_hi,   g_qn_hi);
    cudaGetSymbolAddress((void**)&qn_lo,   g_qn_lo);
    cudaGetSymbolAddress((void**)&kr_hi,   g_kr_hi);
    cudaGetSymbolAddress((void**)&kr_lo,   g_kr_lo);
    cudaGetSymbolAddress((void**)&kipn_hi, g_kipn_hi);
    cudaGetSymbolAddress((void**)&kipn_lo, g_kipn_lo);
    cudaGetSymbolAddress((void**)&vt,      g_vt);
    cudaGetSymbolAddress((void**)&vipt,    g_vipt);

    // ---- batched conversions ----
    {
        const int n4w = HIDN * HIDN / 4;            // 2359296
        CSet a = { Wq, wq_hi, wq_lo, n4w };
        CSet b = { Wk, wk_hi, wk_lo, n4w };
        CSet c = { Wv, wv_hi, wv_lo, n4w };
        CSet d = { Wo, wo_hi, wo_lo, n4w };
        cvt_multi<<<dim3((n4w + 255) / 256, 4), 256>>>(a, b, c, d);
    }
    {
        const int n4ipw = HIDN * IPDIM / 4;         // 884736
        const int n4h   = S_LEN * HIDN / 4;         // 1572864
        const int n4ip  = IPSEQ * IPDIM / 4;        // 147456
        CSet a = { Wk_ip, wkip_hi, wkip_lo, n4ipw };
        CSet b = { Wv_ip, wvip_hi, wvip_lo, n4ipw };
        CSet c = { hidden, hb_hi, hb_lo, n4h };
        CSet d = { iph, ip_hi, ip_lo, n4ip };
        cvt_multi<<<dim3((n4h + 255) / 256, 4), 256>>>(a, b, c, d);
    }

    cudaFuncSetAttribute(gemm_mma_f, cudaFuncAttributeMaxDynamicSharedMemorySize, GEMM_DSMEM);
    cudaFuncSetAttribute(attn_mma, cudaFuncAttributeMaxDynamicSharedMemorySize, ATT_SMEM);

    // ---- fused QKV projection (one launch, 1152 CTAs) ----
    {
        GSet sq = { wq_hi, wq_lo, bq, q };
        GSet sk = { wk_hi, wk_lo, bk, k };
        GSet sv = { wv_hi, wv_lo, bv, v };
        gemm_mma_f<<<dim3(3 * (HIDN / 128), S_LEN / 128), 256, GEMM_DSMEM>>>(
            hb_hi, hb_lo, sq, sk, sv, HIDN / 128, HIDN, HIDN);
    }
    // ---- fused IP K/V projection ----
    {
        GSet sk = { wkip_hi, wkip_lo, bk_ip, kip };
        GSet sv = { wvip_hi, wvip_lo, bv_ip, vip };
        gemm_mma_f<<<dim3(2 * (HIDN / 128), IPSEQ / 128), 256, GEMM_DSMEM>>>(
            ip_hi, ip_lo, sk, sv, sv, HIDN / 128, HIDN, IPDIM);
    }

    prep_q_kernel  <<<dim3(S_LEN, NH), 128>>>(q, sinp, cosp, qscale, qr_hi, qr_lo, qn_hi, qn_lo);
    prep_k_kernel  <<<dim3(S_LEN, NH), 128>>>(k, sinp, cosp, kr_hi, kr_lo);
    prep_kip_kernel<<<dim3(IPSEQ, NH), 128>>>(kip, kscale, kipn_hi, kipn_lo);
    transpose_half <<<dim3(S_LEN / 32, HD / 32, NH), 256>>>(v, vt, S_LEN);
    transpose_half <<<dim3(IPSEQ / 32, HD / 32, NH), 256>>>(vip, vipt, IPSEQ);

    attn_mma<<<dim3(S_LEN / 128, NH), 256, ATT_SMEM>>>(
        qr_hi, qr_lo, qn_hi, qn_lo, kr_hi, kr_lo, kipn_hi, kipn_lo, vt, vipt, ao);

    // ---- output projection ----
    {
        const int n4ao = S_LEN * HIDN / 4;
        CSet a = { ao, ao_hi, ao_lo, n4ao };
        cvt_multi<<<dim3((n4ao + 255) / 256, 1), 256>>>(a, a, a, a);
        GSet so = { wo_hi, wo_lo, bo, (float*)d_out };
        gemm_mma_f<<<dim3(HIDN / 128, S_LEN / 128), 256, GEMM_DSMEM>>>(
            ao_hi, ao_lo, so, so, so, HIDN / 128, HIDN, HIDN);
    }
}